// round 1
// baseline (speedup 1.0000x reference)
#include <cuda_runtime.h>
#include <cuda_bf16.h>
#include <cstdint>

// Problem constants (match reference)
#define NN 100000
#define EE 1600000
#define NFEAT 256
#define NHID 64
#define NHEADS 4
#define HCAT 256   // NHEADS*NHID
#define NCLASS 32
#define ALPHA 0.2f

// ---------------- scratch (device globals; no allocation at runtime) -------
__device__ float g_Wcat[NFEAT * HCAT];          // 256x256 concatenated head weights
__device__ float g_hcat[(long long)NN * HCAT];  // layer-1 pre-attention features
__device__ float g_x1[(long long)NN * HCAT];    // layer-1 output (elu'd, concat)
__device__ float g_ss[NN * NHEADS];
__device__ float g_sd[NN * NHEADS];
__device__ int   g_deg[NN];
__device__ int   g_rowptr[NN + 1];
__device__ int   g_cursor[NN];
__device__ int   g_col[EE];
__device__ int   g_blocksums[1024];
__device__ float g_h2[(long long)NN * NCLASS];
__device__ float g_ss2[NN];
__device__ float g_sd2[NN];

__device__ __forceinline__ float eluf(float v) { return v > 0.f ? v : expm1f(v); }
__device__ __forceinline__ float lrelu(float v) { return v > 0.f ? v : ALPHA * v; }

// ---------------- prep: build Wcat[k, h*64+c] = W_heads[h,k,c]; zero deg ----
__global__ void prep_kernel(const float* __restrict__ Wh, int n) {
    int i = blockIdx.x * blockDim.x + threadIdx.x;
    if (i < NHEADS * NFEAT * NHID) {
        int h = i >> 14;          // / (256*64)
        int rem = i & 16383;
        int k = rem >> 6;
        int c = rem & 63;
        g_Wcat[k * HCAT + (h << 6) + c] = Wh[i];
    }
    if (i < n) g_deg[i] = 0;
}

// ---------------- GEMM1: hcat = x @ Wcat   (M=n, N=256, K=256) -------------
__global__ __launch_bounds__(256) void sgemm1_kernel(const float* __restrict__ A, int M) {
    const int K = NFEAT, N = HCAT;
    __shared__ float As[16][128];
    __shared__ float Bs[16][128];
    int tid = threadIdx.x;
    int blockRow = blockIdx.y * 128;
    int blockCol = blockIdx.x * 128;

    int aRow = tid >> 2;           // 0..63
    int aCol4 = (tid & 3) * 4;     // 0,4,8,12
    int bRow = tid >> 5;           // 0..7
    int bCol4 = (tid & 31) * 4;

    int tr = (tid >> 4) * 8;       // 0..120
    int tc = (tid & 15) * 8;

    float acc[8][8];
#pragma unroll
    for (int i = 0; i < 8; i++)
#pragma unroll
        for (int j = 0; j < 8; j++) acc[i][j] = 0.f;

    for (int k0 = 0; k0 < K; k0 += 16) {
#pragma unroll
        for (int i = 0; i < 2; i++) {
            int r = aRow + i * 64;
            int gr = blockRow + r;
            float4 v = (gr < M) ? *(const float4*)(A + (long long)gr * K + k0 + aCol4)
                                : make_float4(0.f, 0.f, 0.f, 0.f);
            As[aCol4 + 0][r] = v.x;
            As[aCol4 + 1][r] = v.y;
            As[aCol4 + 2][r] = v.z;
            As[aCol4 + 3][r] = v.w;
        }
#pragma unroll
        for (int i = 0; i < 2; i++) {
            int r = bRow + i * 8;
            float4 v = *(const float4*)(g_Wcat + (k0 + r) * N + blockCol + bCol4);
            *(float4*)(&Bs[r][bCol4]) = v;
        }
        __syncthreads();
#pragma unroll
        for (int kk = 0; kk < 16; kk++) {
            float4 ra0 = *(const float4*)(&As[kk][tr]);
            float4 ra1 = *(const float4*)(&As[kk][tr + 4]);
            float4 rb0 = *(const float4*)(&Bs[kk][tc]);
            float4 rb1 = *(const float4*)(&Bs[kk][tc + 4]);
            float ra[8] = {ra0.x, ra0.y, ra0.z, ra0.w, ra1.x, ra1.y, ra1.z, ra1.w};
            float rb[8] = {rb0.x, rb0.y, rb0.z, rb0.w, rb1.x, rb1.y, rb1.z, rb1.w};
#pragma unroll
            for (int i = 0; i < 8; i++)
#pragma unroll
                for (int j = 0; j < 8; j++) acc[i][j] += ra[i] * rb[j];
        }
        __syncthreads();
    }
#pragma unroll
    for (int i = 0; i < 8; i++) {
        int gr = blockRow + tr + i;
        if (gr < M) {
            float4* cp = (float4*)(g_hcat + (long long)gr * N + blockCol + tc);
            cp[0] = make_float4(acc[i][0], acc[i][1], acc[i][2], acc[i][3]);
            cp[1] = make_float4(acc[i][4], acc[i][5], acc[i][6], acc[i][7]);
        }
    }
}

// ---------------- attention scores layer 1 (warp per node) -----------------
__global__ void attn1_kernel(const float* __restrict__ ah, int n) {
    int w = (blockIdx.x * blockDim.x + threadIdx.x) >> 5;
    int lane = threadIdx.x & 31;
    if (w >= n) return;
    int hd = lane >> 3;
    const float4* hp = (const float4*)(g_hcat + (long long)w * HCAT);
    float4 v0 = hp[lane * 2];
    float4 v1 = hp[lane * 2 + 1];
    const float* a1 = ah + hd * 128 + (lane & 7) * 8;  // a_heads[h][:64] slice
    const float* a2 = a1 + 64;                          // a_heads[h][64:] slice
    float s1 = v0.x * a1[0] + v0.y * a1[1] + v0.z * a1[2] + v0.w * a1[3] +
               v1.x * a1[4] + v1.y * a1[5] + v1.z * a1[6] + v1.w * a1[7];
    float s2 = v0.x * a2[0] + v0.y * a2[1] + v0.z * a2[2] + v0.w * a2[3] +
               v1.x * a2[4] + v1.y * a2[5] + v1.z * a2[6] + v1.w * a2[7];
#pragma unroll
    for (int off = 4; off; off >>= 1) {
        s1 += __shfl_xor_sync(0xffffffffu, s1, off);
        s2 += __shfl_xor_sync(0xffffffffu, s2, off);
    }
    if ((lane & 7) == 0) {
        g_ss[w * NHEADS + hd] = s1;
        g_sd[w * NHEADS + hd] = s2;
    }
}

// ---------------- CSR construction -----------------------------------------
__global__ void hist_kernel(const int* __restrict__ src, int e) {
    int i = blockIdx.x * blockDim.x + threadIdx.x;
    if (i < e) atomicAdd(&g_deg[src[i]], 1);
}

__global__ __launch_bounds__(1024) void scan1_kernel(int n) {
    __shared__ int s[1024];
    int t = threadIdx.x;
    int idx = blockIdx.x * 1024 + t;
    int v = (idx < n) ? g_deg[idx] : 0;
    s[t] = v;
    __syncthreads();
#pragma unroll
    for (int off = 1; off < 1024; off <<= 1) {
        int x = (t >= off) ? s[t - off] : 0;
        __syncthreads();
        s[t] += x;
        __syncthreads();
    }
    if (idx < n) g_rowptr[idx] = s[t] - v;   // local exclusive
    if (t == 1023) g_blocksums[blockIdx.x] = s[1023];
}

__global__ __launch_bounds__(1024) void scan2_kernel(int nb) {
    __shared__ int s[1024];
    int t = threadIdx.x;
    int v = (t < nb) ? g_blocksums[t] : 0;
    s[t] = v;
    __syncthreads();
#pragma unroll
    for (int off = 1; off < 1024; off <<= 1) {
        int x = (t >= off) ? s[t - off] : 0;
        __syncthreads();
        s[t] += x;
        __syncthreads();
    }
    if (t < nb) g_blocksums[t] = s[t] - v;   // exclusive
}

__global__ void scan3_kernel(int n, int e) {
    int i = blockIdx.x * blockDim.x + threadIdx.x;
    if (i < n) {
        int r = g_rowptr[i] + g_blocksums[i >> 10];
        g_rowptr[i] = r;
        g_cursor[i] = r;
    }
    if (i == 0) g_rowptr[n] = e;
}

__global__ void scatter_kernel(const int* __restrict__ src, const int* __restrict__ dst, int e) {
    int i = blockIdx.x * blockDim.x + threadIdx.x;
    if (i < e) {
        int s = src[i];
        int p = atomicAdd(&g_cursor[s], 1);
        g_col[p] = dst[i];
    }
}

// ---------------- layer-1 aggregation (warp per src node) ------------------
__global__ void agg1_kernel(int n) {
    int w = (blockIdx.x * blockDim.x + threadIdx.x) >> 5;
    int lane = threadIdx.x & 31;
    if (w >= n) return;
    int start = g_rowptr[w];
    int end = g_rowptr[w + 1];
    int hd = lane >> 3;
    float ss4 = (lane < 4) ? g_ss[w * NHEADS + lane] : 0.f;
    float4 acc0 = make_float4(0.f, 0.f, 0.f, 0.f);
    float4 acc1 = make_float4(0.f, 0.f, 0.f, 0.f);
    float rs4 = 0.f;
    const float4* hp = (const float4*)g_hcat;
    for (int idx = start; idx < end; idx++) {
        int d = g_col[idx];
        float e4 = 0.f;
        if (lane < 4) {
            float s = ss4 + g_sd[d * NHEADS + lane];
            e4 = __expf(-lrelu(s));
            rs4 += e4;
        }
        float e = __shfl_sync(0xffffffffu, e4, hd);
        long long base = (long long)d * 64 + lane * 2;
        float4 v0 = hp[base];
        float4 v1 = hp[base + 1];
        acc0.x += e * v0.x; acc0.y += e * v0.y; acc0.z += e * v0.z; acc0.w += e * v0.w;
        acc1.x += e * v1.x; acc1.y += e * v1.y; acc1.z += e * v1.z; acc1.w += e * v1.w;
    }
    float rs = __shfl_sync(0xffffffffu, rs4, hd);
    float inv = 1.f / rs;
    float4 o0, o1;
    o0.x = eluf(acc0.x * inv); o0.y = eluf(acc0.y * inv);
    o0.z = eluf(acc0.z * inv); o0.w = eluf(acc0.w * inv);
    o1.x = eluf(acc1.x * inv); o1.y = eluf(acc1.y * inv);
    o1.z = eluf(acc1.z * inv); o1.w = eluf(acc1.w * inv);
    float4* xp = (float4*)(g_x1 + (long long)w * HCAT);
    xp[lane * 2] = o0;
    xp[lane * 2 + 1] = o1;
}

// ---------------- GEMM2 + layer-2 scores (warp per row) --------------------
__global__ __launch_bounds__(256) void gemm2_kernel(const float* __restrict__ Wout,
                                                    const float* __restrict__ aout, int n) {
    __shared__ float Ws[NFEAT * NCLASS];  // 256*32 floats = 32KB
    int t = threadIdx.x;
    for (int i = t; i < NFEAT * NCLASS; i += blockDim.x) Ws[i] = Wout[i];
    __syncthreads();
    int warp = t >> 5, lane = t & 31;
    int row = blockIdx.x * 8 + warp;
    if (row >= n) return;
    const float* xr = g_x1 + (long long)row * HCAT;
    float acc = 0.f;
#pragma unroll
    for (int kb = 0; kb < 8; kb++) {
        float xv = xr[kb * 32 + lane];
#pragma unroll
        for (int j = 0; j < 32; j++) {
            acc += __shfl_sync(0xffffffffu, xv, j) * Ws[(kb * 32 + j) * NCLASS + lane];
        }
    }
    g_h2[(long long)row * NCLASS + lane] = acc;
    float p1 = acc * aout[lane];
    float p2 = acc * aout[32 + lane];
#pragma unroll
    for (int off = 16; off; off >>= 1) {
        p1 += __shfl_xor_sync(0xffffffffu, p1, off);
        p2 += __shfl_xor_sync(0xffffffffu, p2, off);
    }
    if (lane == 0) {
        g_ss2[row] = p1;
        g_sd2[row] = p2;
    }
}

// ---------------- layer-2 aggregation + elu + log_softmax ------------------
__global__ void agg2_kernel(float* __restrict__ out, int n) {
    int w = (blockIdx.x * blockDim.x + threadIdx.x) >> 5;
    int lane = threadIdx.x & 31;
    if (w >= n) return;
    int start = g_rowptr[w];
    int end = g_rowptr[w + 1];
    float ssn = g_ss2[w];
    float acc = 0.f, rs = 0.f;
    for (int idx = start; idx < end; idx++) {
        int d = g_col[idx];
        float e = __expf(-lrelu(ssn + g_sd2[d]));
        acc += e * g_h2[(long long)d * NCLASS + lane];
        rs += e;
    }
    float v = eluf(acc / rs);
    float m = v;
#pragma unroll
    for (int off = 16; off; off >>= 1) m = fmaxf(m, __shfl_xor_sync(0xffffffffu, m, off));
    float ex = __expf(v - m);
    float sum = ex;
#pragma unroll
    for (int off = 16; off; off >>= 1) sum += __shfl_xor_sync(0xffffffffu, sum, off);
    out[(long long)w * NCLASS + lane] = v - m - logf(sum);
}

// ---------------- launch ----------------------------------------------------
extern "C" void kernel_launch(void* const* d_in, const int* in_sizes, int n_in,
                              void* d_out, int out_size) {
    const float* x = (const float*)d_in[0];
    const int* edge = (const int*)d_in[1];
    const float* W_heads = (const float*)d_in[2];
    const float* a_heads = (const float*)d_in[3];
    const float* W_out = (const float*)d_in[4];
    const float* a_out = (const float*)d_in[5];
    float* out = (float*)d_out;

    int n = in_sizes[0] / NFEAT;       // 100000
    int e = in_sizes[1] / 2;           // 1600000
    const int* src = edge;
    const int* dst = edge + e;

    int prep_elems = NHEADS * NFEAT * NHID;  // 65536 (>= n? no, n=100000)
    int prep_grid = ((prep_elems > n ? prep_elems : n) + 255) / 256;
    prep_kernel<<<prep_grid, 256>>>(W_heads, n);

    dim3 g1(HCAT / 128, (n + 127) / 128);
    sgemm1_kernel<<<g1, 256>>>(x, n);

    int nwarp_blocks = (n + 7) / 8;  // 8 warps per 256-thread block
    attn1_kernel<<<nwarp_blocks, 256>>>(a_heads, n);

    hist_kernel<<<(e + 255) / 256, 256>>>(src, e);
    int nb = (n + 1023) / 1024;
    scan1_kernel<<<nb, 1024>>>(n);
    scan2_kernel<<<1, 1024>>>(nb);
    scan3_kernel<<<(n + 255) / 256, 256>>>(n, e);
    scatter_kernel<<<(e + 255) / 256, 256>>>(src, dst, e);

    agg1_kernel<<<nwarp_blocks, 256>>>(n);
    gemm2_kernel<<<nwarp_blocks, 256>>>(W_out, a_out, n);
    agg2_kernel<<<nwarp_blocks, 256>>>(out, n);
}

// round 2
// speedup vs baseline: 1.2463x; 1.2463x over previous
#include <cuda_runtime.h>
#include <cuda_bf16.h>
#include <cstdint>

// Problem constants (match reference)
#define NN 100000
#define EE 1600000
#define NFEAT 256
#define NHID 64
#define NHEADS 4
#define HCAT 256   // NHEADS*NHID
#define NCLASS 32
#define ALPHA 0.2f

#define MPAD 128   // row padding so GEMM needs no bounds checks

// ---------------- scratch (device globals; no allocation at runtime) -------
__device__ __nv_bfloat16 g_Whi[NFEAT * HCAT];
__device__ __nv_bfloat16 g_Wlo[NFEAT * HCAT];
__device__ __nv_bfloat16 g_xhi[(size_t)(NN + MPAD) * NFEAT];
__device__ __nv_bfloat16 g_xlo[(size_t)(NN + MPAD) * NFEAT];
__device__ float g_hcat[(size_t)(NN + MPAD) * HCAT];  // layer-1 pre-attention features
__device__ float g_x1[(size_t)NN * HCAT];             // layer-1 output (elu'd, concat)
__device__ float g_ss[NN * NHEADS];
__device__ float g_sd[NN * NHEADS];
__device__ int   g_deg[NN];
__device__ int   g_rowptr[NN + 1];
__device__ int   g_cursor[NN];
__device__ int   g_col[EE];
__device__ int   g_blocksums[1024];
__device__ float g_h2[(size_t)NN * NCLASS];
__device__ float g_ss2[NN];
__device__ float g_sd2[NN];

__device__ __forceinline__ float eluf(float v) { return v > 0.f ? v : expm1f(v); }
__device__ __forceinline__ float lrelu(float v) { return v > 0.f ? v : ALPHA * v; }

// ---------------- prep: split W_heads into bf16 hi/lo, concat layout --------
__global__ void prep_kernel(const float* __restrict__ Wh, int n) {
    int i = blockIdx.x * blockDim.x + threadIdx.x;
    if (i < NHEADS * NFEAT * NHID) {
        int h = i >> 14;          // / (256*64)
        int rem = i & 16383;
        int k = rem >> 6;
        int c = rem & 63;
        float w = Wh[i];
        __nv_bfloat16 hi = __float2bfloat16_rn(w);
        float lo = w - __bfloat162float(hi);
        int dst = k * HCAT + (h << 6) + c;
        g_Whi[dst] = hi;
        g_Wlo[dst] = __float2bfloat16_rn(lo);
    }
    if (i < n) g_deg[i] = 0;
}

// ---------------- split x into bf16 hi/lo (8 floats per thread) ------------
__global__ void convx_kernel(const float* __restrict__ x, int total8) {
    int i = blockIdx.x * blockDim.x + threadIdx.x;
    if (i >= total8) return;
    const float4* xp = (const float4*)x;
    float4 v0 = xp[i * 2];
    float4 v1 = xp[i * 2 + 1];
    float v[8] = {v0.x, v0.y, v0.z, v0.w, v1.x, v1.y, v1.z, v1.w};
    __nv_bfloat16 hi[8], lo[8];
#pragma unroll
    for (int j = 0; j < 8; j++) {
        hi[j] = __float2bfloat16_rn(v[j]);
        float r = v[j] - __bfloat162float(hi[j]);
        lo[j] = __float2bfloat16_rn(r);
    }
    *(uint4*)(g_xhi + (size_t)i * 8) = *(uint4*)hi;
    *(uint4*)(g_xlo + (size_t)i * 8) = *(uint4*)lo;
}

// ---------------- tensor-core GEMM1: hcat = x @ Wcat (bf16 3-pass split) ---
__device__ __forceinline__ void ldsm4(uint32_t& r0, uint32_t& r1, uint32_t& r2, uint32_t& r3, uint32_t addr) {
    asm volatile("ldmatrix.sync.aligned.m8n8.x4.shared.b16 {%0,%1,%2,%3}, [%4];"
                 : "=r"(r0), "=r"(r1), "=r"(r2), "=r"(r3) : "r"(addr));
}
__device__ __forceinline__ void ldsm4t(uint32_t& r0, uint32_t& r1, uint32_t& r2, uint32_t& r3, uint32_t addr) {
    asm volatile("ldmatrix.sync.aligned.m8n8.x4.trans.shared.b16 {%0,%1,%2,%3}, [%4];"
                 : "=r"(r0), "=r"(r1), "=r"(r2), "=r"(r3) : "r"(addr));
}
__device__ __forceinline__ void mma16816(float* c, const uint32_t* a, uint32_t b0, uint32_t b1) {
    asm volatile("mma.sync.aligned.m16n8k16.row.col.f32.bf16.bf16.f32 "
                 "{%0,%1,%2,%3}, {%4,%5,%6,%7}, {%8,%9}, {%0,%1,%2,%3};"
                 : "+f"(c[0]), "+f"(c[1]), "+f"(c[2]), "+f"(c[3])
                 : "r"(a[0]), "r"(a[1]), "r"(a[2]), "r"(a[3]), "r"(b0), "r"(b1));
}
__device__ __forceinline__ void cpa16(uint32_t s, const void* g) {
    asm volatile("cp.async.cg.shared.global [%0], [%1], 16;" :: "r"(s), "l"(g));
}

// smem stage layout (bytes): Ahi[128][40]b16, Alo, Bhi[32][136]b16, Blo
#define G1_SS     37888
#define G1_OFF_AH 0
#define G1_OFF_AL 10240
#define G1_OFF_BH 20480
#define G1_OFF_BL 29184
#define G1_SMEM   (2 * G1_SS)

__global__ __launch_bounds__(256, 2) void mma_gemm1(int M) {
    extern __shared__ __align__(16) char dsm[];
    uint32_t sbase = (uint32_t)__cvta_generic_to_shared(dsm);

    int tid = threadIdx.x;
    int lane = tid & 31, warp = tid >> 5;
    int warpM = (warp >> 1) * 32, warpN = (warp & 1) * 64;
    int blockRow = blockIdx.y * 128, blockCol = blockIdx.x * 128;

    // global->smem load coords
    int arow0 = tid >> 2,          ac0 = (tid & 3) * 8;
    int arow1 = (tid + 256) >> 2;  // ac same pattern: ((tid+256)&3)*8 == ac0
    int brow0 = tid >> 4,          bc0 = (tid & 15) * 8;
    int brow1 = (tid + 256) >> 4;

    const __nv_bfloat16* gAh0 = g_xhi + (size_t)(blockRow + arow0) * NFEAT + ac0;
    const __nv_bfloat16* gAh1 = g_xhi + (size_t)(blockRow + arow1) * NFEAT + ac0;
    const __nv_bfloat16* gAl0 = g_xlo + (size_t)(blockRow + arow0) * NFEAT + ac0;
    const __nv_bfloat16* gAl1 = g_xlo + (size_t)(blockRow + arow1) * NFEAT + ac0;
    const __nv_bfloat16* gBh0 = g_Whi + (size_t)brow0 * HCAT + blockCol + bc0;
    const __nv_bfloat16* gBh1 = g_Whi + (size_t)brow1 * HCAT + blockCol + bc0;
    const __nv_bfloat16* gBl0 = g_Wlo + (size_t)brow0 * HCAT + blockCol + bc0;
    const __nv_bfloat16* gBl1 = g_Wlo + (size_t)brow1 * HCAT + blockCol + bc0;

    uint32_t sA0 = (uint32_t)(arow0 * 40 + ac0) * 2;
    uint32_t sA1 = (uint32_t)(arow1 * 40 + ac0) * 2;
    uint32_t sB0 = (uint32_t)(brow0 * 136 + bc0) * 2;
    uint32_t sB1 = (uint32_t)(brow1 * 136 + bc0) * 2;

    float acc[2][8][4];
#pragma unroll
    for (int a = 0; a < 2; a++)
#pragma unroll
        for (int b = 0; b < 8; b++)
#pragma unroll
            for (int c = 0; c < 4; c++) acc[a][b][c] = 0.f;

    // issue loads for chunk k0 into stage st
    auto load_chunk = [&](int kc, int st) {
        uint32_t sb = sbase + st * G1_SS;
        int k0 = kc * 32;
        cpa16(sb + G1_OFF_AH + sA0, gAh0 + k0);
        cpa16(sb + G1_OFF_AH + sA1, gAh1 + k0);
        cpa16(sb + G1_OFF_AL + sA0, gAl0 + k0);
        cpa16(sb + G1_OFF_AL + sA1, gAl1 + k0);
        cpa16(sb + G1_OFF_BH + sB0, gBh0 + (size_t)k0 * HCAT);
        cpa16(sb + G1_OFF_BH + sB1, gBh1 + (size_t)k0 * HCAT);
        cpa16(sb + G1_OFF_BL + sB0, gBl0 + (size_t)k0 * HCAT);
        cpa16(sb + G1_OFF_BL + sB1, gBl1 + (size_t)k0 * HCAT);
        asm volatile("cp.async.commit_group;");
    };

    load_chunk(0, 0);

    int laneRow = lane & 15;
    int laneSeg = (lane >> 4) * 8;

    for (int c = 0; c < 8; c++) {
        int cur = c & 1;
        if (c < 7) load_chunk(c + 1, cur ^ 1);
        if (c < 7) { asm volatile("cp.async.wait_group 1;"); }
        else       { asm volatile("cp.async.wait_group 0;"); }
        __syncthreads();

        uint32_t sb = sbase + cur * G1_SS;
#pragma unroll
        for (int kk = 0; kk < 32; kk += 16) {
            uint32_t ah[2][4], al[2][4];
#pragma unroll
            for (int mt = 0; mt < 2; mt++) {
                uint32_t ad = sb + G1_OFF_AH +
                    2u * (uint32_t)((warpM + mt * 16 + laneRow) * 40 + kk + laneSeg);
                ldsm4(ah[mt][0], ah[mt][1], ah[mt][2], ah[mt][3], ad);
                ldsm4(al[mt][0], al[mt][1], al[mt][2], al[mt][3], ad + (G1_OFF_AL - G1_OFF_AH));
            }
#pragma unroll
            for (int nt = 0; nt < 4; nt++) {
                uint32_t bd = sb + G1_OFF_BH +
                    2u * (uint32_t)((kk + laneRow) * 136 + warpN + nt * 16 + laneSeg);
                uint32_t bh0, bh1, bh2, bh3, bl0, bl1, bl2, bl3;
                ldsm4t(bh0, bh1, bh2, bh3, bd);
                ldsm4t(bl0, bl1, bl2, bl3, bd + (G1_OFF_BL - G1_OFF_BH));
#pragma unroll
                for (int mt = 0; mt < 2; mt++) {
                    mma16816(acc[mt][2 * nt],     ah[mt], bh0, bh1);
                    mma16816(acc[mt][2 * nt],     al[mt], bh0, bh1);
                    mma16816(acc[mt][2 * nt],     ah[mt], bl0, bl1);
                    mma16816(acc[mt][2 * nt + 1], ah[mt], bh2, bh3);
                    mma16816(acc[mt][2 * nt + 1], al[mt], bh2, bh3);
                    mma16816(acc[mt][2 * nt + 1], ah[mt], bl2, bl3);
                }
            }
        }
        __syncthreads();
    }

    // epilogue: write fp32 hcat (arrays padded, no guards needed)
#pragma unroll
    for (int mt = 0; mt < 2; mt++) {
#pragma unroll
        for (int n8 = 0; n8 < 8; n8++) {
            int r = blockRow + warpM + mt * 16 + (lane >> 2);
            int cc = blockCol + warpN + n8 * 8 + (lane & 3) * 2;
            float2 lo2 = make_float2(acc[mt][n8][0], acc[mt][n8][1]);
            float2 hi2 = make_float2(acc[mt][n8][2], acc[mt][n8][3]);
            *(float2*)(g_hcat + (size_t)r * HCAT + cc) = lo2;
            *(float2*)(g_hcat + (size_t)(r + 8) * HCAT + cc) = hi2;
        }
    }
}

// ---------------- attention scores layer 1 (warp per node) -----------------
__global__ void attn1_kernel(const float* __restrict__ ah, int n) {
    int w = (blockIdx.x * blockDim.x + threadIdx.x) >> 5;
    int lane = threadIdx.x & 31;
    if (w >= n) return;
    int hd = lane >> 3;
    const float4* hp = (const float4*)(g_hcat + (size_t)w * HCAT);
    float4 v0 = hp[lane * 2];
    float4 v1 = hp[lane * 2 + 1];
    const float* a1 = ah + hd * 128 + (lane & 7) * 8;
    const float* a2 = a1 + 64;
    float s1 = v0.x * a1[0] + v0.y * a1[1] + v0.z * a1[2] + v0.w * a1[3] +
               v1.x * a1[4] + v1.y * a1[5] + v1.z * a1[6] + v1.w * a1[7];
    float s2 = v0.x * a2[0] + v0.y * a2[1] + v0.z * a2[2] + v0.w * a2[3] +
               v1.x * a2[4] + v1.y * a2[5] + v1.z * a2[6] + v1.w * a2[7];
#pragma unroll
    for (int off = 4; off; off >>= 1) {
        s1 += __shfl_xor_sync(0xffffffffu, s1, off);
        s2 += __shfl_xor_sync(0xffffffffu, s2, off);
    }
    if ((lane & 7) == 0) {
        g_ss[w * NHEADS + hd] = s1;
        g_sd[w * NHEADS + hd] = s2;
    }
}

// ---------------- CSR construction -----------------------------------------
__global__ void hist_kernel(const int* __restrict__ src, int e) {
    int i = blockIdx.x * blockDim.x + threadIdx.x;
    if (i < e) atomicAdd(&g_deg[src[i]], 1);
}

__global__ __launch_bounds__(1024) void scan1_kernel(int n) {
    __shared__ int s[1024];
    int t = threadIdx.x;
    int idx = blockIdx.x * 1024 + t;
    int v = (idx < n) ? g_deg[idx] : 0;
    s[t] = v;
    __syncthreads();
#pragma unroll
    for (int off = 1; off < 1024; off <<= 1) {
        int x = (t >= off) ? s[t - off] : 0;
        __syncthreads();
        s[t] += x;
        __syncthreads();
    }
    if (idx < n) g_rowptr[idx] = s[t] - v;   // local exclusive
    if (t == 1023) g_blocksums[blockIdx.x] = s[1023];
}

__global__ __launch_bounds__(1024) void scan2_kernel(int nb) {
    __shared__ int s[1024];
    int t = threadIdx.x;
    int v = (t < nb) ? g_blocksums[t] : 0;
    s[t] = v;
    __syncthreads();
#pragma unroll
    for (int off = 1; off < 1024; off <<= 1) {
        int x = (t >= off) ? s[t - off] : 0;
        __syncthreads();
        s[t] += x;
        __syncthreads();
    }
    if (t < nb) g_blocksums[t] = s[t] - v;   // exclusive
}

__global__ void scan3_kernel(int n, int e) {
    int i = blockIdx.x * blockDim.x + threadIdx.x;
    if (i < n) {
        int r = g_rowptr[i] + g_blocksums[i >> 10];
        g_rowptr[i] = r;
        g_cursor[i] = r;
    }
    if (i == 0) g_rowptr[n] = e;
}

__global__ void scatter_kernel(const int* __restrict__ src, const int* __restrict__ dst, int e) {
    int i = blockIdx.x * blockDim.x + threadIdx.x;
    if (i < e) {
        int s = src[i];
        int p = atomicAdd(&g_cursor[s], 1);
        g_col[p] = dst[i];
    }
}

// ---------------- layer-1 aggregation (warp per src node) ------------------
__global__ void agg1_kernel(int n) {
    int w = (blockIdx.x * blockDim.x + threadIdx.x) >> 5;
    int lane = threadIdx.x & 31;
    if (w >= n) return;
    int start = g_rowptr[w];
    int end = g_rowptr[w + 1];
    int hd = lane >> 3;
    float ss4 = (lane < 4) ? g_ss[w * NHEADS + lane] : 0.f;
    float4 acc0 = make_float4(0.f, 0.f, 0.f, 0.f);
    float4 acc1 = make_float4(0.f, 0.f, 0.f, 0.f);
    float rs4 = 0.f;
    const float4* hp = (const float4*)g_hcat;
    for (int idx = start; idx < end; idx++) {
        int d = g_col[idx];
        float e4 = 0.f;
        if (lane < 4) {
            float s = ss4 + g_sd[d * NHEADS + lane];
            e4 = __expf(-lrelu(s));
            rs4 += e4;
        }
        float e = __shfl_sync(0xffffffffu, e4, hd);
        size_t base = (size_t)d * 64 + lane * 2;
        float4 v0 = hp[base];
        float4 v1 = hp[base + 1];
        acc0.x += e * v0.x; acc0.y += e * v0.y; acc0.z += e * v0.z; acc0.w += e * v0.w;
        acc1.x += e * v1.x; acc1.y += e * v1.y; acc1.z += e * v1.z; acc1.w += e * v1.w;
    }
    float rs = __shfl_sync(0xffffffffu, rs4, hd);
    float inv = 1.f / rs;
    float4 o0, o1;
    o0.x = eluf(acc0.x * inv); o0.y = eluf(acc0.y * inv);
    o0.z = eluf(acc0.z * inv); o0.w = eluf(acc0.w * inv);
    o1.x = eluf(acc1.x * inv); o1.y = eluf(acc1.y * inv);
    o1.z = eluf(acc1.z * inv); o1.w = eluf(acc1.w * inv);
    float4* xp = (float4*)(g_x1 + (size_t)w * HCAT);
    xp[lane * 2] = o0;
    xp[lane * 2 + 1] = o1;
}

// ---------------- GEMM2 + layer-2 scores (warp per row) --------------------
__global__ __launch_bounds__(256) void gemm2_kernel(const float* __restrict__ Wout,
                                                    const float* __restrict__ aout, int n) {
    __shared__ float Ws[NFEAT * NCLASS];  // 256*32 floats = 32KB
    int t = threadIdx.x;
    for (int i = t; i < NFEAT * NCLASS; i += blockDim.x) Ws[i] = Wout[i];
    __syncthreads();
    int warp = t >> 5, lane = t & 31;
    int row = blockIdx.x * 8 + warp;
    if (row >= n) return;
    const float* xr = g_x1 + (size_t)row * HCAT;
    float acc = 0.f;
#pragma unroll
    for (int kb = 0; kb < 8; kb++) {
        float xv = xr[kb * 32 + lane];
#pragma unroll
        for (int j = 0; j < 32; j++) {
            acc += __shfl_sync(0xffffffffu, xv, j) * Ws[(kb * 32 + j) * NCLASS + lane];
        }
    }
    g_h2[(size_t)row * NCLASS + lane] = acc;
    float p1 = acc * aout[lane];
    float p2 = acc * aout[32 + lane];
#pragma unroll
    for (int off = 16; off; off >>= 1) {
        p1 += __shfl_xor_sync(0xffffffffu, p1, off);
        p2 += __shfl_xor_sync(0xffffffffu, p2, off);
    }
    if (lane == 0) {
        g_ss2[row] = p1;
        g_sd2[row] = p2;
    }
}

// ---------------- layer-2 aggregation + elu + log_softmax ------------------
__global__ void agg2_kernel(float* __restrict__ out, int n) {
    int w = (blockIdx.x * blockDim.x + threadIdx.x) >> 5;
    int lane = threadIdx.x & 31;
    if (w >= n) return;
    int start = g_rowptr[w];
    int end = g_rowptr[w + 1];
    float ssn = g_ss2[w];
    float acc = 0.f, rs = 0.f;
    for (int idx = start; idx < end; idx++) {
        int d = g_col[idx];
        float e = __expf(-lrelu(ssn + g_sd2[d]));
        acc += e * g_h2[(size_t)d * NCLASS + lane];
        rs += e;
    }
    float v = eluf(acc / rs);
    float m = v;
#pragma unroll
    for (int off = 16; off; off >>= 1) m = fmaxf(m, __shfl_xor_sync(0xffffffffu, m, off));
    float ex = __expf(v - m);
    float sum = ex;
#pragma unroll
    for (int off = 16; off; off >>= 1) sum += __shfl_xor_sync(0xffffffffu, sum, off);
    out[(size_t)w * NCLASS + lane] = v - m - logf(sum);
}

// ---------------- launch ----------------------------------------------------
extern "C" void kernel_launch(void* const* d_in, const int* in_sizes, int n_in,
                              void* d_out, int out_size) {
    const float* x = (const float*)d_in[0];
    const int* edge = (const int*)d_in[1];
    const float* W_heads = (const float*)d_in[2];
    const float* a_heads = (const float*)d_in[3];
    const float* W_out = (const float*)d_in[4];
    const float* a_out = (const float*)d_in[5];
    float* out = (float*)d_out;

    int n = in_sizes[0] / NFEAT;       // 100000
    int e = in_sizes[1] / 2;           // 1600000
    const int* src = edge;
    const int* dst = edge + e;

    static bool attr_set = false;
    if (!attr_set) {
        cudaFuncSetAttribute(mma_gemm1, cudaFuncAttributeMaxDynamicSharedMemorySize, G1_SMEM);
        attr_set = true;
    }

    int prep_elems = NHEADS * NFEAT * NHID;
    int prep_grid = ((prep_elems > n ? prep_elems : n) + 255) / 256;
    prep_kernel<<<prep_grid, 256>>>(W_heads, n);

    int total8 = n * NFEAT / 8;
    convx_kernel<<<(total8 + 255) / 256, 256>>>(x, total8);

    dim3 g1(HCAT / 128, (n + 127) / 128);
    mma_gemm1<<<g1, 256, G1_SMEM>>>(n);

    int nwarp_blocks = (n + 7) / 8;  // 8 warps per 256-thread block
    attn1_kernel<<<nwarp_blocks, 256>>>(a_heads, n);

    hist_kernel<<<(e + 255) / 256, 256>>>(src, e);
    int nb = (n + 1023) / 1024;
    scan1_kernel<<<nb, 1024>>>(n);
    scan2_kernel<<<1, 1024>>>(nb);
    scan3_kernel<<<(n + 255) / 256, 256>>>(n, e);
    scatter_kernel<<<(e + 255) / 256, 256>>>(src, dst, e);

    agg1_kernel<<<nwarp_blocks, 256>>>(n);
    gemm2_kernel<<<nwarp_blocks, 256>>>(W_out, a_out, n);
    agg2_kernel<<<nwarp_blocks, 256>>>(out, n);
}

// round 3
// speedup vs baseline: 1.9566x; 1.5699x over previous
#include <cuda_runtime.h>
#include <cuda_bf16.h>
#include <cstdint>

// Problem constants (match reference)
#define NN 100000
#define EE 1600000
#define NFEAT 256
#define NHID 64
#define NHEADS 4
#define HCAT 256   // NHEADS*NHID
#define NCLASS 32
#define ALPHA 0.2f

#define MPAD 128   // row padding so GEMMs need no bounds checks

// ---------------- scratch (device globals; no allocation at runtime) -------
__device__ __nv_bfloat16 g_Whi[NFEAT * HCAT];
__device__ __nv_bfloat16 g_Wlo[NFEAT * HCAT];
__device__ __nv_bfloat16 g_W2hi[HCAT * NCLASS];
__device__ __nv_bfloat16 g_W2lo[HCAT * NCLASS];
__device__ __nv_bfloat16 g_xhi[(size_t)(NN + MPAD) * NFEAT];
__device__ __nv_bfloat16 g_xlo[(size_t)(NN + MPAD) * NFEAT];
__device__ float g_hcat[(size_t)(NN + MPAD) * HCAT];      // layer-1 features
__device__ __nv_bfloat16 g_x1hi[(size_t)(NN + MPAD) * HCAT];
__device__ __nv_bfloat16 g_x1lo[(size_t)(NN + MPAD) * HCAT];
__device__ float g_ss[(NN + MPAD) * NHEADS];
__device__ float g_sd[(NN + MPAD) * NHEADS];
__device__ int   g_deg[NN];
__device__ int   g_rowptr[NN + 1];
__device__ int   g_cursor[NN];
__device__ int   g_col[EE];
__device__ int   g_blocksums[1024];
__device__ float g_h2[(size_t)(NN + MPAD) * NCLASS];
__device__ float g_ss2[NN + MPAD];
__device__ float g_sd2[NN + MPAD];

__device__ __forceinline__ float eluf(float v) { return v > 0.f ? v : expm1f(v); }
__device__ __forceinline__ float lrelu(float v) { return v > 0.f ? v : ALPHA * v; }

// ---------------- prep: split W_heads/W_out into bf16 hi/lo -----------------
__global__ void prep_kernel(const float* __restrict__ Wh, const float* __restrict__ W2, int n) {
    int i = blockIdx.x * blockDim.x + threadIdx.x;
    if (i < NHEADS * NFEAT * NHID) {
        int h = i >> 14;
        int rem = i & 16383;
        int k = rem >> 6;
        int c = rem & 63;
        float w = Wh[i];
        __nv_bfloat16 hi = __float2bfloat16_rn(w);
        float lo = w - __bfloat162float(hi);
        int dst = k * HCAT + (h << 6) + c;
        g_Whi[dst] = hi;
        g_Wlo[dst] = __float2bfloat16_rn(lo);
    }
    if (i < HCAT * NCLASS) {
        float w = W2[i];
        __nv_bfloat16 hi = __float2bfloat16_rn(w);
        float lo = w - __bfloat162float(hi);
        g_W2hi[i] = hi;
        g_W2lo[i] = __float2bfloat16_rn(lo);
    }
    if (i < n) g_deg[i] = 0;
}

// ---------------- split x into bf16 hi/lo (8 floats per thread) ------------
__global__ void convx_kernel(const float* __restrict__ x, int total8) {
    int i = blockIdx.x * blockDim.x + threadIdx.x;
    if (i >= total8) return;
    const float4* xp = (const float4*)x;
    float4 v0 = xp[i * 2];
    float4 v1 = xp[i * 2 + 1];
    float v[8] = {v0.x, v0.y, v0.z, v0.w, v1.x, v1.y, v1.z, v1.w};
    __nv_bfloat16 hi[8], lo[8];
#pragma unroll
    for (int j = 0; j < 8; j++) {
        hi[j] = __float2bfloat16_rn(v[j]);
        float r = v[j] - __bfloat162float(hi[j]);
        lo[j] = __float2bfloat16_rn(r);
    }
    *(uint4*)(g_xhi + (size_t)i * 8) = *(uint4*)hi;
    *(uint4*)(g_xlo + (size_t)i * 8) = *(uint4*)lo;
}

// ---------------- mma helpers -----------------------------------------------
__device__ __forceinline__ void ldsm4(uint32_t& r0, uint32_t& r1, uint32_t& r2, uint32_t& r3, uint32_t addr) {
    asm volatile("ldmatrix.sync.aligned.m8n8.x4.shared.b16 {%0,%1,%2,%3}, [%4];"
                 : "=r"(r0), "=r"(r1), "=r"(r2), "=r"(r3) : "r"(addr));
}
__device__ __forceinline__ void ldsm4t(uint32_t& r0, uint32_t& r1, uint32_t& r2, uint32_t& r3, uint32_t addr) {
    asm volatile("ldmatrix.sync.aligned.m8n8.x4.trans.shared.b16 {%0,%1,%2,%3}, [%4];"
                 : "=r"(r0), "=r"(r1), "=r"(r2), "=r"(r3) : "r"(addr));
}
__device__ __forceinline__ void mma16816(float* c, const uint32_t* a, uint32_t b0, uint32_t b1) {
    asm volatile("mma.sync.aligned.m16n8k16.row.col.f32.bf16.bf16.f32 "
                 "{%0,%1,%2,%3}, {%4,%5,%6,%7}, {%8,%9}, {%0,%1,%2,%3};"
                 : "+f"(c[0]), "+f"(c[1]), "+f"(c[2]), "+f"(c[3])
                 : "r"(a[0]), "r"(a[1]), "r"(a[2]), "r"(a[3]), "r"(b0), "r"(b1));
}
__device__ __forceinline__ void cpa16(uint32_t s, const void* g) {
    asm volatile("cp.async.cg.shared.global [%0], [%1], 16;" :: "r"(s), "l"(g));
}

// ---------------- GEMM1 + fused layer-1 attention scores --------------------
// smem stage layout (bytes): Ahi[128][40]b16, Alo, Bhi[32][136]b16, Blo
#define G1_SS     37888
#define G1_OFF_AH 0
#define G1_OFF_AL 10240
#define G1_OFF_BH 20480
#define G1_OFF_BL 29184
#define G1_SMEM   (2 * G1_SS)

__global__ __launch_bounds__(256, 2) void mma_gemm1(const float* __restrict__ ah, int M) {
    extern __shared__ __align__(16) char dsm[];
    uint32_t sbase = (uint32_t)__cvta_generic_to_shared(dsm);

    int tid = threadIdx.x;
    int lane = tid & 31, warp = tid >> 5;
    int warpM = (warp >> 1) * 32, warpN = (warp & 1) * 64;
    int blockRow = blockIdx.y * 128, blockCol = blockIdx.x * 128;

    int arow0 = tid >> 2,          ac0 = (tid & 3) * 8;
    int arow1 = (tid + 256) >> 2;
    int brow0 = tid >> 4,          bc0 = (tid & 15) * 8;
    int brow1 = (tid + 256) >> 4;

    const __nv_bfloat16* gAh0 = g_xhi + (size_t)(blockRow + arow0) * NFEAT + ac0;
    const __nv_bfloat16* gAh1 = g_xhi + (size_t)(blockRow + arow1) * NFEAT + ac0;
    const __nv_bfloat16* gAl0 = g_xlo + (size_t)(blockRow + arow0) * NFEAT + ac0;
    const __nv_bfloat16* gAl1 = g_xlo + (size_t)(blockRow + arow1) * NFEAT + ac0;
    const __nv_bfloat16* gBh0 = g_Whi + (size_t)brow0 * HCAT + blockCol + bc0;
    const __nv_bfloat16* gBh1 = g_Whi + (size_t)brow1 * HCAT + blockCol + bc0;
    const __nv_bfloat16* gBl0 = g_Wlo + (size_t)brow0 * HCAT + blockCol + bc0;
    const __nv_bfloat16* gBl1 = g_Wlo + (size_t)brow1 * HCAT + blockCol + bc0;

    uint32_t sA0 = (uint32_t)(arow0 * 40 + ac0) * 2;
    uint32_t sA1 = (uint32_t)(arow1 * 40 + ac0) * 2;
    uint32_t sB0 = (uint32_t)(brow0 * 136 + bc0) * 2;
    uint32_t sB1 = (uint32_t)(brow1 * 136 + bc0) * 2;

    float acc[2][8][4];
#pragma unroll
    for (int a = 0; a < 2; a++)
#pragma unroll
        for (int b = 0; b < 8; b++)
#pragma unroll
            for (int c = 0; c < 4; c++) acc[a][b][c] = 0.f;

    auto load_chunk = [&](int kc, int st) {
        uint32_t sb = sbase + st * G1_SS;
        int k0 = kc * 32;
        cpa16(sb + G1_OFF_AH + sA0, gAh0 + k0);
        cpa16(sb + G1_OFF_AH + sA1, gAh1 + k0);
        cpa16(sb + G1_OFF_AL + sA0, gAl0 + k0);
        cpa16(sb + G1_OFF_AL + sA1, gAl1 + k0);
        cpa16(sb + G1_OFF_BH + sB0, gBh0 + (size_t)k0 * HCAT);
        cpa16(sb + G1_OFF_BH + sB1, gBh1 + (size_t)k0 * HCAT);
        cpa16(sb + G1_OFF_BL + sB0, gBl0 + (size_t)k0 * HCAT);
        cpa16(sb + G1_OFF_BL + sB1, gBl1 + (size_t)k0 * HCAT);
        asm volatile("cp.async.commit_group;");
    };

    load_chunk(0, 0);

    int laneRow = lane & 15;
    int laneSeg = (lane >> 4) * 8;

    for (int c = 0; c < 8; c++) {
        int cur = c & 1;
        if (c < 7) load_chunk(c + 1, cur ^ 1);
        if (c < 7) { asm volatile("cp.async.wait_group 1;"); }
        else       { asm volatile("cp.async.wait_group 0;"); }
        __syncthreads();

        uint32_t sb = sbase + cur * G1_SS;
#pragma unroll
        for (int kk = 0; kk < 32; kk += 16) {
            uint32_t ahf[2][4], alf[2][4];
#pragma unroll
            for (int mt = 0; mt < 2; mt++) {
                uint32_t ad = sb + G1_OFF_AH +
                    2u * (uint32_t)((warpM + mt * 16 + laneRow) * 40 + kk + laneSeg);
                ldsm4(ahf[mt][0], ahf[mt][1], ahf[mt][2], ahf[mt][3], ad);
                ldsm4(alf[mt][0], alf[mt][1], alf[mt][2], alf[mt][3], ad + (G1_OFF_AL - G1_OFF_AH));
            }
#pragma unroll
            for (int nt = 0; nt < 4; nt++) {
                uint32_t bd = sb + G1_OFF_BH +
                    2u * (uint32_t)((kk + laneRow) * 136 + warpN + nt * 16 + laneSeg);
                uint32_t bh0, bh1, bh2, bh3, bl0, bl1, bl2, bl3;
                ldsm4t(bh0, bh1, bh2, bh3, bd);
                ldsm4t(bl0, bl1, bl2, bl3, bd + (G1_OFF_BL - G1_OFF_BH));
#pragma unroll
                for (int mt = 0; mt < 2; mt++) {
                    mma16816(acc[mt][2 * nt],     ahf[mt], bh0, bh1);
                    mma16816(acc[mt][2 * nt],     alf[mt], bh0, bh1);
                    mma16816(acc[mt][2 * nt],     ahf[mt], bl0, bl1);
                    mma16816(acc[mt][2 * nt + 1], ahf[mt], bh2, bh3);
                    mma16816(acc[mt][2 * nt + 1], alf[mt], bh2, bh3);
                    mma16816(acc[mt][2 * nt + 1], ahf[mt], bl2, bl3);
                }
            }
        }
        __syncthreads();
    }

    // epilogue: write fp32 hcat + fused attention scores
#pragma unroll
    for (int mt = 0; mt < 2; mt++) {
#pragma unroll
        for (int n8 = 0; n8 < 8; n8++) {
            int r = blockRow + warpM + mt * 16 + (lane >> 2);
            int cc = blockCol + warpN + n8 * 8 + (lane & 3) * 2;
            *(float2*)(g_hcat + (size_t)r * HCAT + cc) = make_float2(acc[mt][n8][0], acc[mt][n8][1]);
            *(float2*)(g_hcat + (size_t)(r + 8) * HCAT + cc) = make_float2(acc[mt][n8][2], acc[mt][n8][3]);
        }
    }

    // scores: this warp's 64 cols = exactly one head
    int hd = (blockCol + warpN) >> 6;
    const float* aH = ah + hd * 128;
    float s_src[2][2] = {{0.f, 0.f}, {0.f, 0.f}};
    float s_dst[2][2] = {{0.f, 0.f}, {0.f, 0.f}};
#pragma unroll
    for (int n8 = 0; n8 < 8; n8++) {
        int cc = n8 * 8 + (lane & 3) * 2;
        float a0 = __ldg(aH + cc),      a1 = __ldg(aH + cc + 1);
        float b0 = __ldg(aH + 64 + cc), b1 = __ldg(aH + 64 + cc + 1);
#pragma unroll
        for (int mt = 0; mt < 2; mt++) {
            s_src[mt][0] += acc[mt][n8][0] * a0 + acc[mt][n8][1] * a1;
            s_dst[mt][0] += acc[mt][n8][0] * b0 + acc[mt][n8][1] * b1;
            s_src[mt][1] += acc[mt][n8][2] * a0 + acc[mt][n8][3] * a1;
            s_dst[mt][1] += acc[mt][n8][2] * b0 + acc[mt][n8][3] * b1;
        }
    }
#pragma unroll
    for (int mt = 0; mt < 2; mt++)
#pragma unroll
        for (int hh = 0; hh < 2; hh++) {
            float s1 = s_src[mt][hh], s2 = s_dst[mt][hh];
            s1 += __shfl_xor_sync(0xffffffffu, s1, 1);
            s1 += __shfl_xor_sync(0xffffffffu, s1, 2);
            s2 += __shfl_xor_sync(0xffffffffu, s2, 1);
            s2 += __shfl_xor_sync(0xffffffffu, s2, 2);
            if ((lane & 3) == 0) {
                int r = blockRow + warpM + mt * 16 + (lane >> 2) + hh * 8;
                g_ss[r * NHEADS + hd] = s1;
                g_sd[r * NHEADS + hd] = s2;
            }
        }
}

// ---------------- CSR construction -----------------------------------------
__global__ void hist_kernel(const int* __restrict__ src, int e) {
    int i = blockIdx.x * blockDim.x + threadIdx.x;
    if (i < e) atomicAdd(&g_deg[src[i]], 1);
}

__global__ __launch_bounds__(1024) void scan1_kernel(int n) {
    __shared__ int s[1024];
    int t = threadIdx.x;
    int idx = blockIdx.x * 1024 + t;
    int v = (idx < n) ? g_deg[idx] : 0;
    s[t] = v;
    __syncthreads();
#pragma unroll
    for (int off = 1; off < 1024; off <<= 1) {
        int x = (t >= off) ? s[t - off] : 0;
        __syncthreads();
        s[t] += x;
        __syncthreads();
    }
    if (idx < n) g_rowptr[idx] = s[t] - v;
    if (t == 1023) g_blocksums[blockIdx.x] = s[1023];
}

__global__ __launch_bounds__(1024) void scan2_kernel(int nb) {
    __shared__ int s[1024];
    int t = threadIdx.x;
    int v = (t < nb) ? g_blocksums[t] : 0;
    s[t] = v;
    __syncthreads();
#pragma unroll
    for (int off = 1; off < 1024; off <<= 1) {
        int x = (t >= off) ? s[t - off] : 0;
        __syncthreads();
        s[t] += x;
        __syncthreads();
    }
    if (t < nb) g_blocksums[t] = s[t] - v;
}

__global__ void scan3_kernel(int n, int e) {
    int i = blockIdx.x * blockDim.x + threadIdx.x;
    if (i < n) {
        int r = g_rowptr[i] + g_blocksums[i >> 10];
        g_rowptr[i] = r;
        g_cursor[i] = r;
    }
    if (i == 0) g_rowptr[n] = e;
}

__global__ void scatter_kernel(const int* __restrict__ src, const int* __restrict__ dst, int e) {
    int i = blockIdx.x * blockDim.x + threadIdx.x;
    if (i < e) {
        int s = src[i];
        int p = atomicAdd(&g_cursor[s], 1);
        g_col[p] = dst[i];
    }
}

// ---------------- layer-1 aggregation (warp per src node) ------------------
__global__ void agg1_kernel(int n) {
    int w = (blockIdx.x * blockDim.x + threadIdx.x) >> 5;
    int lane = threadIdx.x & 31;
    if (w >= n) return;
    int start = g_rowptr[w];
    int end = g_rowptr[w + 1];
    int hd = lane >> 3;
    float ss4 = (lane < 4) ? g_ss[w * NHEADS + lane] : 0.f;
    float4 acc0 = make_float4(0.f, 0.f, 0.f, 0.f);
    float4 acc1 = make_float4(0.f, 0.f, 0.f, 0.f);
    float rs4 = 0.f;
    const float4* hp = (const float4*)g_hcat;

    int idx = start;
    for (; idx + 1 < end; idx += 2) {
        int d0 = g_col[idx], d1 = g_col[idx + 1];
        float e40 = 0.f, e41 = 0.f;
        if (lane < 4) {
            e40 = __expf(-lrelu(ss4 + g_sd[d0 * NHEADS + lane]));
            e41 = __expf(-lrelu(ss4 + g_sd[d1 * NHEADS + lane]));
            rs4 += e40 + e41;
        }
        float e0 = __shfl_sync(0xffffffffu, e40, hd);
        float e1 = __shfl_sync(0xffffffffu, e41, hd);
        size_t b0 = (size_t)d0 * 64 + lane * 2;
        size_t b1 = (size_t)d1 * 64 + lane * 2;
        float4 u0 = hp[b0], u1 = hp[b0 + 1];
        float4 v0 = hp[b1], v1 = hp[b1 + 1];
        acc0.x += e0 * u0.x + e1 * v0.x; acc0.y += e0 * u0.y + e1 * v0.y;
        acc0.z += e0 * u0.z + e1 * v0.z; acc0.w += e0 * u0.w + e1 * v0.w;
        acc1.x += e0 * u1.x + e1 * v1.x; acc1.y += e0 * u1.y + e1 * v1.y;
        acc1.z += e0 * u1.z + e1 * v1.z; acc1.w += e0 * u1.w + e1 * v1.w;
    }
    if (idx < end) {
        int d = g_col[idx];
        float e4 = 0.f;
        if (lane < 4) {
            e4 = __expf(-lrelu(ss4 + g_sd[d * NHEADS + lane]));
            rs4 += e4;
        }
        float e = __shfl_sync(0xffffffffu, e4, hd);
        size_t base = (size_t)d * 64 + lane * 2;
        float4 u0 = hp[base], u1 = hp[base + 1];
        acc0.x += e * u0.x; acc0.y += e * u0.y; acc0.z += e * u0.z; acc0.w += e * u0.w;
        acc1.x += e * u1.x; acc1.y += e * u1.y; acc1.z += e * u1.z; acc1.w += e * u1.w;
    }

    float rs = __shfl_sync(0xffffffffu, rs4, hd);
    float inv = 1.f / rs;
    float v[8] = {eluf(acc0.x * inv), eluf(acc0.y * inv), eluf(acc0.z * inv), eluf(acc0.w * inv),
                  eluf(acc1.x * inv), eluf(acc1.y * inv), eluf(acc1.z * inv), eluf(acc1.w * inv)};
    __nv_bfloat16 hi8[8], lo8[8];
#pragma unroll
    for (int j = 0; j < 8; j++) {
        hi8[j] = __float2bfloat16_rn(v[j]);
        float r = v[j] - __bfloat162float(hi8[j]);
        lo8[j] = __float2bfloat16_rn(r);
    }
    *(uint4*)(g_x1hi + (size_t)w * HCAT + lane * 8) = *(uint4*)hi8;
    *(uint4*)(g_x1lo + (size_t)w * HCAT + lane * 8) = *(uint4*)lo8;
}

// ---------------- GEMM2 (tensor cores) + fused layer-2 scores ---------------
// smem (bf16 units): Ah[128][264], Al, Bh[256][40], Bl
#define G2_OFF_AH 0
#define G2_OFF_AL 67584
#define G2_OFF_BH 135168
#define G2_OFF_BL 155648
#define G2_SMEM   176128

__global__ __launch_bounds__(256) void mma_gemm2(const float* __restrict__ aout) {
    extern __shared__ __align__(16) char dsm[];
    uint32_t sb = (uint32_t)__cvta_generic_to_shared(dsm);
    int tid = threadIdx.x;
    int blockRow = blockIdx.x * 128;

    // load A block (x1 hi/lo, 128 rows x 256 cols)
#pragma unroll
    for (int it = 0; it < 16; it++) {
        int chunk = it * 256 + tid;           // 0..4095
        int row = chunk >> 5, col8 = (chunk & 31) * 8;
        size_t goff = (size_t)(blockRow + row) * HCAT + col8;
        uint32_t sa = sb + G2_OFF_AH + (uint32_t)(row * 264 + col8) * 2;
        cpa16(sa, g_x1hi + goff);
        cpa16(sa + (G2_OFF_AL - G2_OFF_AH), g_x1lo + goff);
    }
    // load B (W2 hi/lo, 256 x 32)
#pragma unroll
    for (int it = 0; it < 4; it++) {
        int chunk = it * 256 + tid;           // 0..1023
        int row = chunk >> 2, col8 = (chunk & 3) * 8;
        uint32_t sB = sb + G2_OFF_BH + (uint32_t)(row * 40 + col8) * 2;
        cpa16(sB, g_W2hi + row * NCLASS + col8);
        cpa16(sB + (G2_OFF_BL - G2_OFF_BH), g_W2lo + row * NCLASS + col8);
    }
    asm volatile("cp.async.commit_group;");
    asm volatile("cp.async.wait_group 0;");
    __syncthreads();

    int warp = tid >> 5, lane = tid & 31;
    int laneRow = lane & 15, laneSeg = (lane >> 4) * 8;
    float acc[4][4];
#pragma unroll
    for (int a = 0; a < 4; a++)
#pragma unroll
        for (int c = 0; c < 4; c++) acc[a][c] = 0.f;

#pragma unroll
    for (int kk = 0; kk < 256; kk += 16) {
        uint32_t ad = sb + G2_OFF_AH + 2u * (uint32_t)((warp * 16 + laneRow) * 264 + kk + laneSeg);
        uint32_t ahf[4], alf[4];
        ldsm4(ahf[0], ahf[1], ahf[2], ahf[3], ad);
        ldsm4(alf[0], alf[1], alf[2], alf[3], ad + (G2_OFF_AL - G2_OFF_AH));
#pragma unroll
        for (int nt = 0; nt < 2; nt++) {
            uint32_t bd = sb + G2_OFF_BH + 2u * (uint32_t)((kk + laneRow) * 40 + nt * 16 + laneSeg);
            uint32_t bh0, bh1, bh2, bh3, bl0, bl1, bl2, bl3;
            ldsm4t(bh0, bh1, bh2, bh3, bd);
            ldsm4t(bl0, bl1, bl2, bl3, bd + (G2_OFF_BL - G2_OFF_BH));
            mma16816(acc[2 * nt],     ahf, bh0, bh1);
            mma16816(acc[2 * nt],     alf, bh0, bh1);
            mma16816(acc[2 * nt],     ahf, bl0, bl1);
            mma16816(acc[2 * nt + 1], ahf, bh2, bh3);
            mma16816(acc[2 * nt + 1], alf, bh2, bh3);
            mma16816(acc[2 * nt + 1], ahf, bl2, bl3);
        }
    }

    // epilogue: write h2 + fused ss2/sd2
    int r0 = blockRow + warp * 16 + (lane >> 2);
    float s1[2] = {0.f, 0.f}, s2[2] = {0.f, 0.f};
#pragma unroll
    for (int n8 = 0; n8 < 4; n8++) {
        int cc = n8 * 8 + (lane & 3) * 2;
        float a0 = __ldg(aout + cc),      a1 = __ldg(aout + cc + 1);
        float b0 = __ldg(aout + 32 + cc), b1 = __ldg(aout + 32 + cc + 1);
        *(float2*)(g_h2 + (size_t)r0 * NCLASS + cc) = make_float2(acc[n8][0], acc[n8][1]);
        *(float2*)(g_h2 + (size_t)(r0 + 8) * NCLASS + cc) = make_float2(acc[n8][2], acc[n8][3]);
        s1[0] += acc[n8][0] * a0 + acc[n8][1] * a1;
        s2[0] += acc[n8][0] * b0 + acc[n8][1] * b1;
        s1[1] += acc[n8][2] * a0 + acc[n8][3] * a1;
        s2[1] += acc[n8][2] * b0 + acc[n8][3] * b1;
    }
#pragma unroll
    for (int hh = 0; hh < 2; hh++) {
        float p1 = s1[hh], p2 = s2[hh];
        p1 += __shfl_xor_sync(0xffffffffu, p1, 1);
        p1 += __shfl_xor_sync(0xffffffffu, p1, 2);
        p2 += __shfl_xor_sync(0xffffffffu, p2, 1);
        p2 += __shfl_xor_sync(0xffffffffu, p2, 2);
        if ((lane & 3) == 0) {
            g_ss2[r0 + hh * 8] = p1;
            g_sd2[r0 + hh * 8] = p2;
        }
    }
}

// ---------------- layer-2 aggregation + elu + log_softmax ------------------
__global__ void agg2_kernel(float* __restrict__ out, int n) {
    int w = (blockIdx.x * blockDim.x + threadIdx.x) >> 5;
    int lane = threadIdx.x & 31;
    if (w >= n) return;
    int start = g_rowptr[w];
    int end = g_rowptr[w + 1];
    float ssn = g_ss2[w];
    float acc = 0.f, rs = 0.f;
    int idx = start;
    for (; idx + 1 < end; idx += 2) {
        int d0 = g_col[idx], d1 = g_col[idx + 1];
        float e0 = __expf(-lrelu(ssn + g_sd2[d0]));
        float e1 = __expf(-lrelu(ssn + g_sd2[d1]));
        acc += e0 * g_h2[(size_t)d0 * NCLASS + lane] + e1 * g_h2[(size_t)d1 * NCLASS + lane];
        rs += e0 + e1;
    }
    if (idx < end) {
        int d = g_col[idx];
        float e = __expf(-lrelu(ssn + g_sd2[d]));
        acc += e * g_h2[(size_t)d * NCLASS + lane];
        rs += e;
    }
    float v = eluf(acc / rs);
    float m = v;
#pragma unroll
    for (int off = 16; off; off >>= 1) m = fmaxf(m, __shfl_xor_sync(0xffffffffu, m, off));
    float ex = __expf(v - m);
    float sum = ex;
#pragma unroll
    for (int off = 16; off; off >>= 1) sum += __shfl_xor_sync(0xffffffffu, sum, off);
    out[(size_t)w * NCLASS + lane] = v - m - logf(sum);
}

// ---------------- launch ----------------------------------------------------
extern "C" void kernel_launch(void* const* d_in, const int* in_sizes, int n_in,
                              void* d_out, int out_size) {
    const float* x = (const float*)d_in[0];
    const int* edge = (const int*)d_in[1];
    const float* W_heads = (const float*)d_in[2];
    const float* a_heads = (const float*)d_in[3];
    const float* W_out = (const float*)d_in[4];
    const float* a_out = (const float*)d_in[5];
    float* out = (float*)d_out;

    int n = in_sizes[0] / NFEAT;       // 100000
    int e = in_sizes[1] / 2;           // 1600000
    const int* src = edge;
    const int* dst = edge + e;

    static bool attr_set = false;
    if (!attr_set) {
        cudaFuncSetAttribute(mma_gemm1, cudaFuncAttributeMaxDynamicSharedMemorySize, G1_SMEM);
        cudaFuncSetAttribute(mma_gemm2, cudaFuncAttributeMaxDynamicSharedMemorySize, G2_SMEM);
        attr_set = true;
    }

    int prep_elems = NHEADS * NFEAT * NHID;
    int prep_grid = ((prep_elems > n ? prep_elems : n) + 255) / 256;
    prep_kernel<<<prep_grid, 256>>>(W_heads, W_out, n);

    int total8 = n * NFEAT / 8;
    convx_kernel<<<(total8 + 255) / 256, 256>>>(x, total8);

    dim3 g1(HCAT / 128, (n + 127) / 128);
    mma_gemm1<<<g1, 256, G1_SMEM>>>(a_heads, n);

    hist_kernel<<<(e + 255) / 256, 256>>>(src, e);
    int nb = (n + 1023) / 1024;
    scan1_kernel<<<nb, 1024>>>(n);
    scan2_kernel<<<1, 1024>>>(nb);
    scan3_kernel<<<(n + 255) / 256, 256>>>(n, e);
    scatter_kernel<<<(e + 255) / 256, 256>>>(src, dst, e);

    int nwarp_blocks = (n + 7) / 8;
    agg1_kernel<<<nwarp_blocks, 256>>>(n);
    mma_gemm2<<<(n + 127) / 128, 256, G2_SMEM>>>(a_out);
    agg2_kernel<<<nwarp_blocks, 256>>>(out, n);
}

// round 4
// speedup vs baseline: 2.1727x; 1.1105x over previous
#include <cuda_runtime.h>
#include <cuda_bf16.h>
#include <cuda_fp16.h>
#include <cstdint>

// Problem constants (match reference)
#define NN 100000
#define EE 1600000
#define NFEAT 256
#define NHID 64
#define NHEADS 4
#define HCAT 256   // NHEADS*NHID
#define NCLASS 32
#define ALPHA 0.2f

#define MPAD 128   // row padding so GEMMs need no bounds checks

// ---------------- scratch (device globals; no allocation at runtime) -------
__device__ __nv_bfloat16 g_Whi[NFEAT * HCAT];
__device__ __nv_bfloat16 g_Wlo[NFEAT * HCAT];
__device__ __nv_bfloat16 g_W2hi[HCAT * NCLASS];
__device__ __nv_bfloat16 g_W2lo[HCAT * NCLASS];
__device__ __nv_bfloat16 g_xhi[(size_t)(NN + MPAD) * NFEAT];
__device__ __nv_bfloat16 g_xlo[(size_t)(NN + MPAD) * NFEAT];
__device__ __half g_hcat[(size_t)(NN + MPAD) * HCAT];     // layer-1 features (fp16)
__device__ __nv_bfloat16 g_x1hi[(size_t)(NN + MPAD) * HCAT];
__device__ __nv_bfloat16 g_x1lo[(size_t)(NN + MPAD) * HCAT];
__device__ float g_ss[(NN + MPAD) * NHEADS];
__device__ float g_sd[(NN + MPAD) * NHEADS];
__device__ int   g_deg[NN];
__device__ int   g_rowptr[NN + 1];
__device__ int   g_cursor[NN];
__device__ int   g_col[EE];
__device__ int   g_blocksums[1024];
__device__ float g_h2[(size_t)(NN + MPAD) * NCLASS];
__device__ float g_ss2[NN + MPAD];
__device__ float g_sd2[NN + MPAD];

__device__ __forceinline__ float eluf(float v) { return v > 0.f ? v : expm1f(v); }
__device__ __forceinline__ float lrelu(float v) { return v > 0.f ? v : ALPHA * v; }

// ---------------- prep: split W_heads/W_out into bf16 hi/lo -----------------
__global__ void prep_kernel(const float* __restrict__ Wh, const float* __restrict__ W2, int n) {
    int i = blockIdx.x * blockDim.x + threadIdx.x;
    if (i < NHEADS * NFEAT * NHID) {
        int h = i >> 14;
        int rem = i & 16383;
        int k = rem >> 6;
        int c = rem & 63;
        float w = Wh[i];
        __nv_bfloat16 hi = __float2bfloat16_rn(w);
        float lo = w - __bfloat162float(hi);
        int dst = k * HCAT + (h << 6) + c;
        g_Whi[dst] = hi;
        g_Wlo[dst] = __float2bfloat16_rn(lo);
    }
    if (i < HCAT * NCLASS) {
        float w = W2[i];
        __nv_bfloat16 hi = __float2bfloat16_rn(w);
        float lo = w - __bfloat162float(hi);
        g_W2hi[i] = hi;
        g_W2lo[i] = __float2bfloat16_rn(lo);
    }
    if (i < n) g_deg[i] = 0;
}

// ---------------- split x into bf16 hi/lo (8 floats per thread) ------------
__global__ void convx_kernel(const float* __restrict__ x, int total8) {
    int i = blockIdx.x * blockDim.x + threadIdx.x;
    if (i >= total8) return;
    const float4* xp = (const float4*)x;
    float4 v0 = xp[i * 2];
    float4 v1 = xp[i * 2 + 1];
    float v[8] = {v0.x, v0.y, v0.z, v0.w, v1.x, v1.y, v1.z, v1.w};
    __nv_bfloat16 hi[8], lo[8];
#pragma unroll
    for (int j = 0; j < 8; j++) {
        hi[j] = __float2bfloat16_rn(v[j]);
        float r = v[j] - __bfloat162float(hi[j]);
        lo[j] = __float2bfloat16_rn(r);
    }
    *(uint4*)(g_xhi + (size_t)i * 8) = *(uint4*)hi;
    *(uint4*)(g_xlo + (size_t)i * 8) = *(uint4*)lo;
}

// ---------------- mma helpers -----------------------------------------------
__device__ __forceinline__ void ldsm4(uint32_t& r0, uint32_t& r1, uint32_t& r2, uint32_t& r3, uint32_t addr) {
    asm volatile("ldmatrix.sync.aligned.m8n8.x4.shared.b16 {%0,%1,%2,%3}, [%4];"
                 : "=r"(r0), "=r"(r1), "=r"(r2), "=r"(r3) : "r"(addr));
}
__device__ __forceinline__ void ldsm4t(uint32_t& r0, uint32_t& r1, uint32_t& r2, uint32_t& r3, uint32_t addr) {
    asm volatile("ldmatrix.sync.aligned.m8n8.x4.trans.shared.b16 {%0,%1,%2,%3}, [%4];"
                 : "=r"(r0), "=r"(r1), "=r"(r2), "=r"(r3) : "r"(addr));
}
__device__ __forceinline__ void mma16816(float* c, const uint32_t* a, uint32_t b0, uint32_t b1) {
    asm volatile("mma.sync.aligned.m16n8k16.row.col.f32.bf16.bf16.f32 "
                 "{%0,%1,%2,%3}, {%4,%5,%6,%7}, {%8,%9}, {%0,%1,%2,%3};"
                 : "+f"(c[0]), "+f"(c[1]), "+f"(c[2]), "+f"(c[3])
                 : "r"(a[0]), "r"(a[1]), "r"(a[2]), "r"(a[3]), "r"(b0), "r"(b1));
}
__device__ __forceinline__ void cpa16(uint32_t s, const void* g) {
    asm volatile("cp.async.cg.shared.global [%0], [%1], 16;" :: "r"(s), "l"(g));
}

// ---------------- GEMM1 + fused layer-1 attention scores --------------------
// smem stage layout (bytes): Ahi[128][40]b16, Alo, Bhi[32][136]b16, Blo
#define G1_SS     37888
#define G1_OFF_AH 0
#define G1_OFF_AL 10240
#define G1_OFF_BH 20480
#define G1_OFF_BL 29184
#define G1_SMEM   (2 * G1_SS)

__global__ __launch_bounds__(256, 2) void mma_gemm1(const float* __restrict__ ah, int M) {
    extern __shared__ __align__(16) char dsm[];
    uint32_t sbase = (uint32_t)__cvta_generic_to_shared(dsm);

    int tid = threadIdx.x;
    int lane = tid & 31, warp = tid >> 5;
    int warpM = (warp >> 1) * 32, warpN = (warp & 1) * 64;
    int blockRow = blockIdx.y * 128, blockCol = blockIdx.x * 128;

    int arow0 = tid >> 2,          ac0 = (tid & 3) * 8;
    int arow1 = (tid + 256) >> 2;
    int brow0 = tid >> 4,          bc0 = (tid & 15) * 8;
    int brow1 = (tid + 256) >> 4;

    const __nv_bfloat16* gAh0 = g_xhi + (size_t)(blockRow + arow0) * NFEAT + ac0;
    const __nv_bfloat16* gAh1 = g_xhi + (size_t)(blockRow + arow1) * NFEAT + ac0;
    const __nv_bfloat16* gAl0 = g_xlo + (size_t)(blockRow + arow0) * NFEAT + ac0;
    const __nv_bfloat16* gAl1 = g_xlo + (size_t)(blockRow + arow1) * NFEAT + ac0;
    const __nv_bfloat16* gBh0 = g_Whi + (size_t)brow0 * HCAT + blockCol + bc0;
    const __nv_bfloat16* gBh1 = g_Whi + (size_t)brow1 * HCAT + blockCol + bc0;
    const __nv_bfloat16* gBl0 = g_Wlo + (size_t)brow0 * HCAT + blockCol + bc0;
    const __nv_bfloat16* gBl1 = g_Wlo + (size_t)brow1 * HCAT + blockCol + bc0;

    uint32_t sA0 = (uint32_t)(arow0 * 40 + ac0) * 2;
    uint32_t sA1 = (uint32_t)(arow1 * 40 + ac0) * 2;
    uint32_t sB0 = (uint32_t)(brow0 * 136 + bc0) * 2;
    uint32_t sB1 = (uint32_t)(brow1 * 136 + bc0) * 2;

    float acc[2][8][4];
#pragma unroll
    for (int a = 0; a < 2; a++)
#pragma unroll
        for (int b = 0; b < 8; b++)
#pragma unroll
            for (int c = 0; c < 4; c++) acc[a][b][c] = 0.f;

    auto load_chunk = [&](int kc, int st) {
        uint32_t sb = sbase + st * G1_SS;
        int k0 = kc * 32;
        cpa16(sb + G1_OFF_AH + sA0, gAh0 + k0);
        cpa16(sb + G1_OFF_AH + sA1, gAh1 + k0);
        cpa16(sb + G1_OFF_AL + sA0, gAl0 + k0);
        cpa16(sb + G1_OFF_AL + sA1, gAl1 + k0);
        cpa16(sb + G1_OFF_BH + sB0, gBh0 + (size_t)k0 * HCAT);
        cpa16(sb + G1_OFF_BH + sB1, gBh1 + (size_t)k0 * HCAT);
        cpa16(sb + G1_OFF_BL + sB0, gBl0 + (size_t)k0 * HCAT);
        cpa16(sb + G1_OFF_BL + sB1, gBl1 + (size_t)k0 * HCAT);
        asm volatile("cp.async.commit_group;");
    };

    load_chunk(0, 0);

    int laneRow = lane & 15;
    int laneSeg = (lane >> 4) * 8;

    for (int c = 0; c < 8; c++) {
        int cur = c & 1;
        if (c < 7) load_chunk(c + 1, cur ^ 1);
        if (c < 7) { asm volatile("cp.async.wait_group 1;"); }
        else       { asm volatile("cp.async.wait_group 0;"); }
        __syncthreads();

        uint32_t sb = sbase + cur * G1_SS;
#pragma unroll
        for (int kk = 0; kk < 32; kk += 16) {
            uint32_t ahf[2][4], alf[2][4];
#pragma unroll
            for (int mt = 0; mt < 2; mt++) {
                uint32_t ad = sb + G1_OFF_AH +
                    2u * (uint32_t)((warpM + mt * 16 + laneRow) * 40 + kk + laneSeg);
                ldsm4(ahf[mt][0], ahf[mt][1], ahf[mt][2], ahf[mt][3], ad);
                ldsm4(alf[mt][0], alf[mt][1], alf[mt][2], alf[mt][3], ad + (G1_OFF_AL - G1_OFF_AH));
            }
#pragma unroll
            for (int nt = 0; nt < 4; nt++) {
                uint32_t bd = sb + G1_OFF_BH +
                    2u * (uint32_t)((kk + laneRow) * 136 + warpN + nt * 16 + laneSeg);
                uint32_t bh0, bh1, bh2, bh3, bl0, bl1, bl2, bl3;
                ldsm4t(bh0, bh1, bh2, bh3, bd);
                ldsm4t(bl0, bl1, bl2, bl3, bd + (G1_OFF_BL - G1_OFF_BH));
#pragma unroll
                for (int mt = 0; mt < 2; mt++) {
                    mma16816(acc[mt][2 * nt],     ahf[mt], bh0, bh1);
                    mma16816(acc[mt][2 * nt],     alf[mt], bh0, bh1);
                    mma16816(acc[mt][2 * nt],     ahf[mt], bl0, bl1);
                    mma16816(acc[mt][2 * nt + 1], ahf[mt], bh2, bh3);
                    mma16816(acc[mt][2 * nt + 1], alf[mt], bh2, bh3);
                    mma16816(acc[mt][2 * nt + 1], ahf[mt], bl2, bl3);
                }
            }
        }
        __syncthreads();
    }

    // epilogue: write fp16 hcat + fused attention scores (from fp32 accs)
#pragma unroll
    for (int mt = 0; mt < 2; mt++) {
#pragma unroll
        for (int n8 = 0; n8 < 8; n8++) {
            int r = blockRow + warpM + mt * 16 + (lane >> 2);
            int cc = blockCol + warpN + n8 * 8 + (lane & 3) * 2;
            __half2 p0 = __floats2half2_rn(acc[mt][n8][0], acc[mt][n8][1]);
            __half2 p1 = __floats2half2_rn(acc[mt][n8][2], acc[mt][n8][3]);
            *(__half2*)(g_hcat + (size_t)r * HCAT + cc) = p0;
            *(__half2*)(g_hcat + (size_t)(r + 8) * HCAT + cc) = p1;
        }
    }

    // scores: this warp's 64 cols = exactly one head
    int hd = (blockCol + warpN) >> 6;
    const float* aH = ah + hd * 128;
    float s_src[2][2] = {{0.f, 0.f}, {0.f, 0.f}};
    float s_dst[2][2] = {{0.f, 0.f}, {0.f, 0.f}};
#pragma unroll
    for (int n8 = 0; n8 < 8; n8++) {
        int cc = n8 * 8 + (lane & 3) * 2;
        float a0 = __ldg(aH + cc),      a1 = __ldg(aH + cc + 1);
        float b0 = __ldg(aH + 64 + cc), b1 = __ldg(aH + 64 + cc + 1);
#pragma unroll
        for (int mt = 0; mt < 2; mt++) {
            s_src[mt][0] += acc[mt][n8][0] * a0 + acc[mt][n8][1] * a1;
            s_dst[mt][0] += acc[mt][n8][0] * b0 + acc[mt][n8][1] * b1;
            s_src[mt][1] += acc[mt][n8][2] * a0 + acc[mt][n8][3] * a1;
            s_dst[mt][1] += acc[mt][n8][2] * b0 + acc[mt][n8][3] * b1;
        }
    }
#pragma unroll
    for (int mt = 0; mt < 2; mt++)
#pragma unroll
        for (int hh = 0; hh < 2; hh++) {
            float s1 = s_src[mt][hh], s2 = s_dst[mt][hh];
            s1 += __shfl_xor_sync(0xffffffffu, s1, 1);
            s1 += __shfl_xor_sync(0xffffffffu, s1, 2);
            s2 += __shfl_xor_sync(0xffffffffu, s2, 1);
            s2 += __shfl_xor_sync(0xffffffffu, s2, 2);
            if ((lane & 3) == 0) {
                int r = blockRow + warpM + mt * 16 + (lane >> 2) + hh * 8;
                g_ss[r * NHEADS + hd] = s1;
                g_sd[r * NHEADS + hd] = s2;
            }
        }
}

// ---------------- CSR construction -----------------------------------------
__global__ void hist_kernel(const int* __restrict__ src, int e) {
    int i = blockIdx.x * blockDim.x + threadIdx.x;
    if (i < e) atomicAdd(&g_deg[src[i]], 1);
}

__global__ __launch_bounds__(1024) void scan1_kernel(int n) {
    __shared__ int s[1024];
    int t = threadIdx.x;
    int idx = blockIdx.x * 1024 + t;
    int v = (idx < n) ? g_deg[idx] : 0;
    s[t] = v;
    __syncthreads();
#pragma unroll
    for (int off = 1; off < 1024; off <<= 1) {
        int x = (t >= off) ? s[t - off] : 0;
        __syncthreads();
        s[t] += x;
        __syncthreads();
    }
    if (idx < n) g_rowptr[idx] = s[t] - v;
    if (t == 1023) g_blocksums[blockIdx.x] = s[1023];
}

__global__ __launch_bounds__(1024) void scan2_kernel(int nb) {
    __shared__ int s[1024];
    int t = threadIdx.x;
    int v = (t < nb) ? g_blocksums[t] : 0;
    s[t] = v;
    __syncthreads();
#pragma unroll
    for (int off = 1; off < 1024; off <<= 1) {
        int x = (t >= off) ? s[t - off] : 0;
        __syncthreads();
        s[t] += x;
        __syncthreads();
    }
    if (t < nb) g_blocksums[t] = s[t] - v;
}

__global__ void scan3_kernel(int n, int e) {
    int i = blockIdx.x * blockDim.x + threadIdx.x;
    if (i < n) {
        int r = g_rowptr[i] + g_blocksums[i >> 10];
        g_rowptr[i] = r;
        g_cursor[i] = r;
    }
    if (i == 0) g_rowptr[n] = e;
}

__global__ void scatter_kernel(const int* __restrict__ src, const int* __restrict__ dst, int e) {
    int i = blockIdx.x * blockDim.x + threadIdx.x;
    if (i < e) {
        int s = src[i];
        int p = atomicAdd(&g_cursor[s], 1);
        g_col[p] = dst[i];
    }
}

// ---------------- layer-1 aggregation (warp per src node, fp16 gather) -----
__device__ __forceinline__ void accum8(float* acc, uint4 r, float e) {
    float2 f0 = __half22float2(*(__half2*)&r.x);
    float2 f1 = __half22float2(*(__half2*)&r.y);
    float2 f2 = __half22float2(*(__half2*)&r.z);
    float2 f3 = __half22float2(*(__half2*)&r.w);
    acc[0] += e * f0.x; acc[1] += e * f0.y;
    acc[2] += e * f1.x; acc[3] += e * f1.y;
    acc[4] += e * f2.x; acc[5] += e * f2.y;
    acc[6] += e * f3.x; acc[7] += e * f3.y;
}

__global__ void agg1_kernel(int n) {
    int w = (blockIdx.x * blockDim.x + threadIdx.x) >> 5;
    int lane = threadIdx.x & 31;
    if (w >= n) return;
    int start = g_rowptr[w];
    int end = g_rowptr[w + 1];
    int hd = lane >> 3;
    float ss_h = (lane < 16) ? g_ss[w * NHEADS + (lane & 3)] : 0.f;
    float acc[8] = {0.f, 0.f, 0.f, 0.f, 0.f, 0.f, 0.f, 0.f};
    float rs16 = 0.f;
    const uint4* hp = (const uint4*)g_hcat;

    int idx = start;
    for (; idx + 4 <= end; idx += 4) {
        int d0 = g_col[idx], d1 = g_col[idx + 1], d2 = g_col[idx + 2], d3 = g_col[idx + 3];
        int dsel = (lane < 4) ? d0 : (lane < 8) ? d1 : (lane < 12) ? d2 : d3;
        float ev = 0.f;
        if (lane < 16) {
            ev = __expf(-lrelu(ss_h + g_sd[dsel * NHEADS + (lane & 3)]));
            rs16 += ev;
        }
        uint4 r0 = hp[(size_t)d0 * 32 + lane];
        uint4 r1 = hp[(size_t)d1 * 32 + lane];
        uint4 r2 = hp[(size_t)d2 * 32 + lane];
        uint4 r3 = hp[(size_t)d3 * 32 + lane];
        float e0 = __shfl_sync(0xffffffffu, ev, hd);
        float e1 = __shfl_sync(0xffffffffu, ev, 4 + hd);
        float e2 = __shfl_sync(0xffffffffu, ev, 8 + hd);
        float e3 = __shfl_sync(0xffffffffu, ev, 12 + hd);
        accum8(acc, r0, e0);
        accum8(acc, r1, e1);
        accum8(acc, r2, e2);
        accum8(acc, r3, e3);
    }
    for (; idx < end; idx++) {
        int d = g_col[idx];
        float ev = 0.f;
        if (lane < 4) {
            ev = __expf(-lrelu(ss_h + g_sd[d * NHEADS + lane]));
            rs16 += ev;
        }
        uint4 r = hp[(size_t)d * 32 + lane];
        float e = __shfl_sync(0xffffffffu, ev, hd);
        accum8(acc, r, e);
    }

    rs16 += __shfl_xor_sync(0xffffffffu, rs16, 4);
    rs16 += __shfl_xor_sync(0xffffffffu, rs16, 8);
    float rs = __shfl_sync(0xffffffffu, rs16, hd);
    float inv = 1.f / rs;

    __nv_bfloat16 hi8[8], lo8[8];
#pragma unroll
    for (int j = 0; j < 8; j++) {
        float v = eluf(acc[j] * inv);
        hi8[j] = __float2bfloat16_rn(v);
        float r = v - __bfloat162float(hi8[j]);
        lo8[j] = __float2bfloat16_rn(r);
    }
    *(uint4*)(g_x1hi + (size_t)w * HCAT + lane * 8) = *(uint4*)hi8;
    *(uint4*)(g_x1lo + (size_t)w * HCAT + lane * 8) = *(uint4*)lo8;
}

// ---------------- GEMM2 (tensor cores) + fused layer-2 scores ---------------
// smem (bf16 units): Ah[128][264], Al, Bh[256][40], Bl
#define G2_OFF_AH 0
#define G2_OFF_AL 67584
#define G2_OFF_BH 135168
#define G2_OFF_BL 155648
#define G2_SMEM   176128

__global__ __launch_bounds__(256) void mma_gemm2(const float* __restrict__ aout) {
    extern __shared__ __align__(16) char dsm[];
    uint32_t sb = (uint32_t)__cvta_generic_to_shared(dsm);
    int tid = threadIdx.x;
    int blockRow = blockIdx.x * 128;

#pragma unroll
    for (int it = 0; it < 16; it++) {
        int chunk = it * 256 + tid;
        int row = chunk >> 5, col8 = (chunk & 31) * 8;
        size_t goff = (size_t)(blockRow + row) * HCAT + col8;
        uint32_t sa = sb + G2_OFF_AH + (uint32_t)(row * 264 + col8) * 2;
        cpa16(sa, g_x1hi + goff);
        cpa16(sa + (G2_OFF_AL - G2_OFF_AH), g_x1lo + goff);
    }
#pragma unroll
    for (int it = 0; it < 4; it++) {
        int chunk = it * 256 + tid;
        int row = chunk >> 2, col8 = (chunk & 3) * 8;
        uint32_t sB = sb + G2_OFF_BH + (uint32_t)(row * 40 + col8) * 2;
        cpa16(sB, g_W2hi + row * NCLASS + col8);
        cpa16(sB + (G2_OFF_BL - G2_OFF_BH), g_W2lo + row * NCLASS + col8);
    }
    asm volatile("cp.async.commit_group;");
    asm volatile("cp.async.wait_group 0;");
    __syncthreads();

    int warp = tid >> 5, lane = tid & 31;
    int laneRow = lane & 15, laneSeg = (lane >> 4) * 8;
    float acc[4][4];
#pragma unroll
    for (int a = 0; a < 4; a++)
#pragma unroll
        for (int c = 0; c < 4; c++) acc[a][c] = 0.f;

#pragma unroll
    for (int kk = 0; kk < 256; kk += 16) {
        uint32_t ad = sb + G2_OFF_AH + 2u * (uint32_t)((warp * 16 + laneRow) * 264 + kk + laneSeg);
        uint32_t ahf[4], alf[4];
        ldsm4(ahf[0], ahf[1], ahf[2], ahf[3], ad);
        ldsm4(alf[0], alf[1], alf[2], alf[3], ad + (G2_OFF_AL - G2_OFF_AH));
#pragma unroll
        for (int nt = 0; nt < 2; nt++) {
            uint32_t bd = sb + G2_OFF_BH + 2u * (uint32_t)((kk + laneRow) * 40 + nt * 16 + laneSeg);
            uint32_t bh0, bh1, bh2, bh3, bl0, bl1, bl2, bl3;
            ldsm4t(bh0, bh1, bh2, bh3, bd);
            ldsm4t(bl0, bl1, bl2, bl3, bd + (G2_OFF_BL - G2_OFF_BH));
            mma16816(acc[2 * nt],     ahf, bh0, bh1);
            mma16816(acc[2 * nt],     alf, bh0, bh1);
            mma16816(acc[2 * nt],     ahf, bl0, bl1);
            mma16816(acc[2 * nt + 1], ahf, bh2, bh3);
            mma16816(acc[2 * nt + 1], alf, bh2, bh3);
            mma16816(acc[2 * nt + 1], ahf, bl2, bl3);
        }
    }

    int r0 = blockRow + warp * 16 + (lane >> 2);
    float s1[2] = {0.f, 0.f}, s2[2] = {0.f, 0.f};
#pragma unroll
    for (int n8 = 0; n8 < 4; n8++) {
        int cc = n8 * 8 + (lane & 3) * 2;
        float a0 = __ldg(aout + cc),      a1 = __ldg(aout + cc + 1);
        float b0 = __ldg(aout + 32 + cc), b1 = __ldg(aout + 32 + cc + 1);
        *(float2*)(g_h2 + (size_t)r0 * NCLASS + cc) = make_float2(acc[n8][0], acc[n8][1]);
        *(float2*)(g_h2 + (size_t)(r0 + 8) * NCLASS + cc) = make_float2(acc[n8][2], acc[n8][3]);
        s1[0] += acc[n8][0] * a0 + acc[n8][1] * a1;
        s2[0] += acc[n8][0] * b0 + acc[n8][1] * b1;
        s1[1] += acc[n8][2] * a0 + acc[n8][3] * a1;
        s2[1] += acc[n8][2] * b0 + acc[n8][3] * b1;
    }
#pragma unroll
    for (int hh = 0; hh < 2; hh++) {
        float p1 = s1[hh], p2 = s2[hh];
        p1 += __shfl_xor_sync(0xffffffffu, p1, 1);
        p1 += __shfl_xor_sync(0xffffffffu, p1, 2);
        p2 += __shfl_xor_sync(0xffffffffu, p2, 1);
        p2 += __shfl_xor_sync(0xffffffffu, p2, 2);
        if ((lane & 3) == 0) {
            g_ss2[r0 + hh * 8] = p1;
            g_sd2[r0 + hh * 8] = p2;
        }
    }
}

// ---------------- layer-2 aggregation + elu + log_softmax ------------------
__global__ void agg2_kernel(float* __restrict__ out, int n) {
    int w = (blockIdx.x * blockDim.x + threadIdx.x) >> 5;
    int lane = threadIdx.x & 31;
    if (w >= n) return;
    int start = g_rowptr[w];
    int end = g_rowptr[w + 1];
    float ssn = g_ss2[w];
    float acc = 0.f, rs = 0.f;
    int idx = start;
    for (; idx + 4 <= end; idx += 4) {
        int d0 = g_col[idx], d1 = g_col[idx + 1], d2 = g_col[idx + 2], d3 = g_col[idx + 3];
        float e0 = __expf(-lrelu(ssn + g_sd2[d0]));
        float e1 = __expf(-lrelu(ssn + g_sd2[d1]));
        float e2 = __expf(-lrelu(ssn + g_sd2[d2]));
        float e3 = __expf(-lrelu(ssn + g_sd2[d3]));
        float h0 = g_h2[(size_t)d0 * NCLASS + lane];
        float h1 = g_h2[(size_t)d1 * NCLASS + lane];
        float h2v = g_h2[(size_t)d2 * NCLASS + lane];
        float h3 = g_h2[(size_t)d3 * NCLASS + lane];
        acc += e0 * h0 + e1 * h1 + e2 * h2v + e3 * h3;
        rs += e0 + e1 + e2 + e3;
    }
    for (; idx < end; idx++) {
        int d = g_col[idx];
        float e = __expf(-lrelu(ssn + g_sd2[d]));
        acc += e * g_h2[(size_t)d * NCLASS + lane];
        rs += e;
    }
    float v = eluf(acc / rs);
    float m = v;
#pragma unroll
    for (int off = 16; off; off >>= 1) m = fmaxf(m, __shfl_xor_sync(0xffffffffu, m, off));
    float ex = __expf(v - m);
    float sum = ex;
#pragma unroll
    for (int off = 16; off; off >>= 1) sum += __shfl_xor_sync(0xffffffffu, sum, off);
    out[(size_t)w * NCLASS + lane] = v - m - logf(sum);
}

// ---------------- launch ----------------------------------------------------
extern "C" void kernel_launch(void* const* d_in, const int* in_sizes, int n_in,
                              void* d_out, int out_size) {
    const float* x = (const float*)d_in[0];
    const int* edge = (const int*)d_in[1];
    const float* W_heads = (const float*)d_in[2];
    const float* a_heads = (const float*)d_in[3];
    const float* W_out = (const float*)d_in[4];
    const float* a_out = (const float*)d_in[5];
    float* out = (float*)d_out;

    int n = in_sizes[0] / NFEAT;       // 100000
    int e = in_sizes[1] / 2;           // 1600000
    const int* src = edge;
    const int* dst = edge + e;

    static bool attr_set = false;
    if (!attr_set) {
        cudaFuncSetAttribute(mma_gemm1, cudaFuncAttributeMaxDynamicSharedMemorySize, G1_SMEM);
        cudaFuncSetAttribute(mma_gemm2, cudaFuncAttributeMaxDynamicSharedMemorySize, G2_SMEM);
        attr_set = true;
    }

    int prep_elems = NHEADS * NFEAT * NHID;
    int prep_grid = ((prep_elems > n ? prep_elems : n) + 255) / 256;
    prep_kernel<<<prep_grid, 256>>>(W_heads, W_out, n);

    int total8 = n * NFEAT / 8;
    convx_kernel<<<(total8 + 255) / 256, 256>>>(x, total8);

    dim3 g1(HCAT / 128, (n + 127) / 128);
    mma_gemm1<<<g1, 256, G1_SMEM>>>(a_heads, n);

    hist_kernel<<<(e + 255) / 256, 256>>>(src, e);
    int nb = (n + 1023) / 1024;
    scan1_kernel<<<nb, 1024>>>(n);
    scan2_kernel<<<1, 1024>>>(nb);
    scan3_kernel<<<(n + 255) / 256, 256>>>(n, e);
    scatter_kernel<<<(e + 255) / 256, 256>>>(src, dst, e);

    int nwarp_blocks = (n + 7) / 8;
    agg1_kernel<<<nwarp_blocks, 256>>>(n);
    mma_gemm2<<<(n + 127) / 128, 256, G2_SMEM>>>(a_out);
    agg2_kernel<<<nwarp_blocks, 256>>>(out, n);
}

// round 5
// speedup vs baseline: 2.5599x; 1.1782x over previous
#include <cuda_runtime.h>
#include <cuda_bf16.h>
#include <cuda_fp16.h>
#include <cstdint>

// Problem constants (match reference)
#define NN 100000
#define EE 1600000
#define NFEAT 256
#define NHID 64
#define NHEADS 4
#define HCAT 256   // NHEADS*NHID
#define NCLASS 32
#define ALPHA 0.2f

#define MPAD 128   // row padding so GEMMs need no bounds checks

// ---------------- scratch (device globals; no allocation at runtime) -------
__device__ __half g_Whi[NFEAT * HCAT];           // W in fp16 (2-pass split: W-lo dropped)
__device__ __half g_W2hi[HCAT * NCLASS];
__device__ __half g_xhi[(size_t)(NN + MPAD) * NFEAT];
__device__ __half g_xlo[(size_t)(NN + MPAD) * NFEAT];
__device__ __half g_hcat[(size_t)(NN + MPAD) * HCAT];     // layer-1 features (fp16)
__device__ __half g_x1hi[(size_t)(NN + MPAD) * HCAT];
__device__ __half g_x1lo[(size_t)(NN + MPAD) * HCAT];
__device__ float g_ss[(NN + MPAD) * NHEADS];
__device__ float g_sd[(NN + MPAD) * NHEADS];
__device__ int   g_deg[NN];
__device__ int   g_rowptr[NN + 1];
__device__ int   g_cursor[NN];
__device__ int   g_col[EE];
__device__ int   g_blocksums[1024];
__device__ float g_h2[(size_t)(NN + MPAD) * NCLASS];
__device__ float g_ss2[NN + MPAD];
__device__ float g_sd2[NN + MPAD];

__device__ __forceinline__ float eluf(float v) { return v > 0.f ? v : expm1f(v); }
__device__ __forceinline__ float lrelu(float v) { return v > 0.f ? v : ALPHA * v; }

// ---------------- prep: W_heads/W_out -> fp16, concat layout; zero deg ------
__global__ void prep_kernel(const float* __restrict__ Wh, const float* __restrict__ W2, int n) {
    int i = blockIdx.x * blockDim.x + threadIdx.x;
    if (i < NHEADS * NFEAT * NHID) {
        int h = i >> 14;
        int rem = i & 16383;
        int k = rem >> 6;
        int c = rem & 63;
        g_Whi[k * HCAT + (h << 6) + c] = __float2half_rn(Wh[i]);
    }
    if (i < HCAT * NCLASS) {
        g_W2hi[i] = __float2half_rn(W2[i]);
    }
    if (i < n) g_deg[i] = 0;
}

// ---------------- split x into fp16 hi/lo (8 floats per thread) ------------
__global__ void convx_kernel(const float* __restrict__ x, int total8) {
    int i = blockIdx.x * blockDim.x + threadIdx.x;
    if (i >= total8) return;
    const float4* xp = (const float4*)x;
    float4 v0 = xp[i * 2];
    float4 v1 = xp[i * 2 + 1];
    float v[8] = {v0.x, v0.y, v0.z, v0.w, v1.x, v1.y, v1.z, v1.w};
    __half hi[8], lo[8];
#pragma unroll
    for (int j = 0; j < 8; j++) {
        hi[j] = __float2half_rn(v[j]);
        float r = v[j] - __half2float(hi[j]);
        lo[j] = __float2half_rn(r);
    }
    *(uint4*)(g_xhi + (size_t)i * 8) = *(uint4*)hi;
    *(uint4*)(g_xlo + (size_t)i * 8) = *(uint4*)lo;
}

// ---------------- mma helpers -----------------------------------------------
__device__ __forceinline__ void ldsm4(uint32_t& r0, uint32_t& r1, uint32_t& r2, uint32_t& r3, uint32_t addr) {
    asm volatile("ldmatrix.sync.aligned.m8n8.x4.shared.b16 {%0,%1,%2,%3}, [%4];"
                 : "=r"(r0), "=r"(r1), "=r"(r2), "=r"(r3) : "r"(addr));
}
__device__ __forceinline__ void ldsm4t(uint32_t& r0, uint32_t& r1, uint32_t& r2, uint32_t& r3, uint32_t addr) {
    asm volatile("ldmatrix.sync.aligned.m8n8.x4.trans.shared.b16 {%0,%1,%2,%3}, [%4];"
                 : "=r"(r0), "=r"(r1), "=r"(r2), "=r"(r3) : "r"(addr));
}
__device__ __forceinline__ void mma16816(float* c, const uint32_t* a, uint32_t b0, uint32_t b1) {
    asm volatile("mma.sync.aligned.m16n8k16.row.col.f32.f16.f16.f32 "
                 "{%0,%1,%2,%3}, {%4,%5,%6,%7}, {%8,%9}, {%0,%1,%2,%3};"
                 : "+f"(c[0]), "+f"(c[1]), "+f"(c[2]), "+f"(c[3])
                 : "r"(a[0]), "r"(a[1]), "r"(a[2]), "r"(a[3]), "r"(b0), "r"(b1));
}
__device__ __forceinline__ void cpa16(uint32_t s, const void* g) {
    asm volatile("cp.async.cg.shared.global [%0], [%1], 16;" :: "r"(s), "l"(g));
}

// ---------------- GEMM1 + fused layer-1 attention scores --------------------
// smem stage layout (bytes): Ahi[128][40]f16, Alo[128][40], Bh[32][136]f16
#define G1_SS     29184
#define G1_OFF_AH 0
#define G1_OFF_AL 10240
#define G1_OFF_BH 20480
#define G1_SMEM   (2 * G1_SS)

__global__ __launch_bounds__(256, 2) void mma_gemm1(const float* __restrict__ ah, int M) {
    extern __shared__ __align__(16) char dsm[];
    uint32_t sbase = (uint32_t)__cvta_generic_to_shared(dsm);

    int tid = threadIdx.x;
    int lane = tid & 31, warp = tid >> 5;
    int warpM = (warp >> 1) * 32, warpN = (warp & 1) * 64;
    int blockRow = blockIdx.y * 128, blockCol = blockIdx.x * 128;

    int arow0 = tid >> 2,          ac0 = (tid & 3) * 8;
    int arow1 = (tid + 256) >> 2;
    int brow0 = tid >> 4,          bc0 = (tid & 15) * 8;
    int brow1 = (tid + 256) >> 4;

    const __half* gAh0 = g_xhi + (size_t)(blockRow + arow0) * NFEAT + ac0;
    const __half* gAh1 = g_xhi + (size_t)(blockRow + arow1) * NFEAT + ac0;
    const __half* gAl0 = g_xlo + (size_t)(blockRow + arow0) * NFEAT + ac0;
    const __half* gAl1 = g_xlo + (size_t)(blockRow + arow1) * NFEAT + ac0;
    const __half* gBh0 = g_Whi + (size_t)brow0 * HCAT + blockCol + bc0;
    const __half* gBh1 = g_Whi + (size_t)brow1 * HCAT + blockCol + bc0;

    uint32_t sA0 = (uint32_t)(arow0 * 40 + ac0) * 2;
    uint32_t sA1 = (uint32_t)(arow1 * 40 + ac0) * 2;
    uint32_t sB0 = (uint32_t)(brow0 * 136 + bc0) * 2;
    uint32_t sB1 = (uint32_t)(brow1 * 136 + bc0) * 2;

    float acc[2][8][4];
#pragma unroll
    for (int a = 0; a < 2; a++)
#pragma unroll
        for (int b = 0; b < 8; b++)
#pragma unroll
            for (int c = 0; c < 4; c++) acc[a][b][c] = 0.f;

    auto load_chunk = [&](int kc, int st) {
        uint32_t sb = sbase + st * G1_SS;
        int k0 = kc * 32;
        cpa16(sb + G1_OFF_AH + sA0, gAh0 + k0);
        cpa16(sb + G1_OFF_AH + sA1, gAh1 + k0);
        cpa16(sb + G1_OFF_AL + sA0, gAl0 + k0);
        cpa16(sb + G1_OFF_AL + sA1, gAl1 + k0);
        cpa16(sb + G1_OFF_BH + sB0, gBh0 + (size_t)k0 * HCAT);
        cpa16(sb + G1_OFF_BH + sB1, gBh1 + (size_t)k0 * HCAT);
        asm volatile("cp.async.commit_group;");
    };

    load_chunk(0, 0);

    int laneRow = lane & 15;
    int laneSeg = (lane >> 4) * 8;

    for (int c = 0; c < 8; c++) {
        int cur = c & 1;
        if (c < 7) load_chunk(c + 1, cur ^ 1);
        if (c < 7) { asm volatile("cp.async.wait_group 1;"); }
        else       { asm volatile("cp.async.wait_group 0;"); }
        __syncthreads();

        uint32_t sb = sbase + cur * G1_SS;
#pragma unroll
        for (int kk = 0; kk < 32; kk += 16) {
            uint32_t ahf[2][4], alf[2][4];
#pragma unroll
            for (int mt = 0; mt < 2; mt++) {
                uint32_t ad = sb + G1_OFF_AH +
                    2u * (uint32_t)((warpM + mt * 16 + laneRow) * 40 + kk + laneSeg);
                ldsm4(ahf[mt][0], ahf[mt][1], ahf[mt][2], ahf[mt][3], ad);
                ldsm4(alf[mt][0], alf[mt][1], alf[mt][2], alf[mt][3], ad + (G1_OFF_AL - G1_OFF_AH));
            }
#pragma unroll
            for (int nt = 0; nt < 4; nt++) {
                uint32_t bd = sb + G1_OFF_BH +
                    2u * (uint32_t)((kk + laneRow) * 136 + warpN + nt * 16 + laneSeg);
                uint32_t bh0, bh1, bh2, bh3;
                ldsm4t(bh0, bh1, bh2, bh3, bd);
#pragma unroll
                for (int mt = 0; mt < 2; mt++) {
                    mma16816(acc[mt][2 * nt],     ahf[mt], bh0, bh1);
                    mma16816(acc[mt][2 * nt],     alf[mt], bh0, bh1);
                    mma16816(acc[mt][2 * nt + 1], ahf[mt], bh2, bh3);
                    mma16816(acc[mt][2 * nt + 1], alf[mt], bh2, bh3);
                }
            }
        }
        __syncthreads();
    }

    // epilogue: write fp16 hcat + fused attention scores (from fp32 accs)
#pragma unroll
    for (int mt = 0; mt < 2; mt++) {
#pragma unroll
        for (int n8 = 0; n8 < 8; n8++) {
            int r = blockRow + warpM + mt * 16 + (lane >> 2);
            int cc = blockCol + warpN + n8 * 8 + (lane & 3) * 2;
            __half2 p0 = __floats2half2_rn(acc[mt][n8][0], acc[mt][n8][1]);
            __half2 p1 = __floats2half2_rn(acc[mt][n8][2], acc[mt][n8][3]);
            *(__half2*)(g_hcat + (size_t)r * HCAT + cc) = p0;
            *(__half2*)(g_hcat + (size_t)(r + 8) * HCAT + cc) = p1;
        }
    }

    // scores: this warp's 64 cols = exactly one head
    int hd = (blockCol + warpN) >> 6;
    const float* aH = ah + hd * 128;
    float s_src[2][2] = {{0.f, 0.f}, {0.f, 0.f}};
    float s_dst[2][2] = {{0.f, 0.f}, {0.f, 0.f}};
#pragma unroll
    for (int n8 = 0; n8 < 8; n8++) {
        int cc = n8 * 8 + (lane & 3) * 2;
        float a0 = __ldg(aH + cc),      a1 = __ldg(aH + cc + 1);
        float b0 = __ldg(aH + 64 + cc), b1 = __ldg(aH + 64 + cc + 1);
#pragma unroll
        for (int mt = 0; mt < 2; mt++) {
            s_src[mt][0] += acc[mt][n8][0] * a0 + acc[mt][n8][1] * a1;
            s_dst[mt][0] += acc[mt][n8][0] * b0 + acc[mt][n8][1] * b1;
            s_src[mt][1] += acc[mt][n8][2] * a0 + acc[mt][n8][3] * a1;
            s_dst[mt][1] += acc[mt][n8][2] * b0 + acc[mt][n8][3] * b1;
        }
    }
#pragma unroll
    for (int mt = 0; mt < 2; mt++)
#pragma unroll
        for (int hh = 0; hh < 2; hh++) {
            float s1 = s_src[mt][hh], s2 = s_dst[mt][hh];
            s1 += __shfl_xor_sync(0xffffffffu, s1, 1);
            s1 += __shfl_xor_sync(0xffffffffu, s1, 2);
            s2 += __shfl_xor_sync(0xffffffffu, s2, 1);
            s2 += __shfl_xor_sync(0xffffffffu, s2, 2);
            if ((lane & 3) == 0) {
                int r = blockRow + warpM + mt * 16 + (lane >> 2) + hh * 8;
                g_ss[r * NHEADS + hd] = s1;
                g_sd[r * NHEADS + hd] = s2;
            }
        }
}

// ---------------- CSR construction -----------------------------------------
__global__ void hist_kernel(const int* __restrict__ src, int e) {
    int i = blockIdx.x * blockDim.x + threadIdx.x;
    if (i < e) atomicAdd(&g_deg[src[i]], 1);
}

__global__ __launch_bounds__(1024) void scan1_kernel(int n) {
    __shared__ int s[1024];
    int t = threadIdx.x;
    int idx = blockIdx.x * 1024 + t;
    int v = (idx < n) ? g_deg[idx] : 0;
    s[t] = v;
    __syncthreads();
#pragma unroll
    for (int off = 1; off < 1024; off <<= 1) {
        int x = (t >= off) ? s[t - off] : 0;
        __syncthreads();
        s[t] += x;
        __syncthreads();
    }
    if (idx < n) g_rowptr[idx] = s[t] - v;
    if (t == 1023) g_blocksums[blockIdx.x] = s[1023];
}

__global__ __launch_bounds__(1024) void scan2_kernel(int nb) {
    __shared__ int s[1024];
    int t = threadIdx.x;
    int v = (t < nb) ? g_blocksums[t] : 0;
    s[t] = v;
    __syncthreads();
#pragma unroll
    for (int off = 1; off < 1024; off <<= 1) {
        int x = (t >= off) ? s[t - off] : 0;
        __syncthreads();
        s[t] += x;
        __syncthreads();
    }
    if (t < nb) g_blocksums[t] = s[t] - v;
}

__global__ void scan3_kernel(int n, int e) {
    int i = blockIdx.x * blockDim.x + threadIdx.x;
    if (i < n) {
        int r = g_rowptr[i] + g_blocksums[i >> 10];
        g_rowptr[i] = r;
        g_cursor[i] = r;
    }
    if (i == 0) g_rowptr[n] = e;
}

__global__ void scatter_kernel(const int* __restrict__ src, const int* __restrict__ dst, int e) {
    int i = blockIdx.x * blockDim.x + threadIdx.x;
    if (i < e) {
        int s = src[i];
        int p = atomicAdd(&g_cursor[s], 1);
        g_col[p] = dst[i];
    }
}

// ---------------- layer-1 aggregation (warp per src node, fp16 gather) -----
__device__ __forceinline__ void accum8(float* acc, uint4 r, float e) {
    float2 f0 = __half22float2(*(__half2*)&r.x);
    float2 f1 = __half22float2(*(__half2*)&r.y);
    float2 f2 = __half22float2(*(__half2*)&r.z);
    float2 f3 = __half22float2(*(__half2*)&r.w);
    acc[0] += e * f0.x; acc[1] += e * f0.y;
    acc[2] += e * f1.x; acc[3] += e * f1.y;
    acc[4] += e * f2.x; acc[5] += e * f2.y;
    acc[6] += e * f3.x; acc[7] += e * f3.y;
}

__global__ void agg1_kernel(int n) {
    int w = (blockIdx.x * blockDim.x + threadIdx.x) >> 5;
    int lane = threadIdx.x & 31;
    if (w >= n) return;
    int start = g_rowptr[w];
    int end = g_rowptr[w + 1];
    int hd = lane >> 3;
    float ss_h = (lane < 16) ? g_ss[w * NHEADS + (lane & 3)] : 0.f;
    float acc[8] = {0.f, 0.f, 0.f, 0.f, 0.f, 0.f, 0.f, 0.f};
    float rs16 = 0.f;
    const uint4* hp = (const uint4*)g_hcat;

    int idx = start;
    for (; idx + 4 <= end; idx += 4) {
        int d0 = g_col[idx], d1 = g_col[idx + 1], d2 = g_col[idx + 2], d3 = g_col[idx + 3];
        int dsel = (lane < 4) ? d0 : (lane < 8) ? d1 : (lane < 12) ? d2 : d3;
        float ev = 0.f;
        if (lane < 16) {
            ev = __expf(-lrelu(ss_h + g_sd[dsel * NHEADS + (lane & 3)]));
            rs16 += ev;
        }
        uint4 r0 = hp[(size_t)d0 * 32 + lane];
        uint4 r1 = hp[(size_t)d1 * 32 + lane];
        uint4 r2 = hp[(size_t)d2 * 32 + lane];
        uint4 r3 = hp[(size_t)d3 * 32 + lane];
        float e0 = __shfl_sync(0xffffffffu, ev, hd);
        float e1 = __shfl_sync(0xffffffffu, ev, 4 + hd);
        float e2 = __shfl_sync(0xffffffffu, ev, 8 + hd);
        float e3 = __shfl_sync(0xffffffffu, ev, 12 + hd);
        accum8(acc, r0, e0);
        accum8(acc, r1, e1);
        accum8(acc, r2, e2);
        accum8(acc, r3, e3);
    }
    for (; idx < end; idx++) {
        int d = g_col[idx];
        float ev = 0.f;
        if (lane < 4) {
            ev = __expf(-lrelu(ss_h + g_sd[d * NHEADS + lane]));
            rs16 += ev;
        }
        uint4 r = hp[(size_t)d * 32 + lane];
        float e = __shfl_sync(0xffffffffu, ev, hd);
        accum8(acc, r, e);
    }

    rs16 += __shfl_xor_sync(0xffffffffu, rs16, 4);
    rs16 += __shfl_xor_sync(0xffffffffu, rs16, 8);
    float rs = __shfl_sync(0xffffffffu, rs16, hd);
    float inv = 1.f / rs;

    __half hi8[8], lo8[8];
#pragma unroll
    for (int j = 0; j < 8; j++) {
        float v = eluf(acc[j] * inv);
        hi8[j] = __float2half_rn(v);
        float r = v - __half2float(hi8[j]);
        lo8[j] = __float2half_rn(r);
    }
    *(uint4*)(g_x1hi + (size_t)w * HCAT + lane * 8) = *(uint4*)hi8;
    *(uint4*)(g_x1lo + (size_t)w * HCAT + lane * 8) = *(uint4*)lo8;
}

// ---------------- GEMM2 (tensor cores) + fused layer-2 scores ---------------
// smem (bytes): Ah[128][264]f16, Al[128][264], Bh[256][40]f16
#define G2_OFF_AH 0
#define G2_OFF_AL 67584
#define G2_OFF_BH 135168
#define G2_SMEM   155648

__global__ __launch_bounds__(256) void mma_gemm2(const float* __restrict__ aout) {
    extern __shared__ __align__(16) char dsm[];
    uint32_t sb = (uint32_t)__cvta_generic_to_shared(dsm);
    int tid = threadIdx.x;
    int blockRow = blockIdx.x * 128;

#pragma unroll
    for (int it = 0; it < 16; it++) {
        int chunk = it * 256 + tid;
        int row = chunk >> 5, col8 = (chunk & 31) * 8;
        size_t goff = (size_t)(blockRow + row) * HCAT + col8;
        uint32_t sa = sb + G2_OFF_AH + (uint32_t)(row * 264 + col8) * 2;
        cpa16(sa, g_x1hi + goff);
        cpa16(sa + (G2_OFF_AL - G2_OFF_AH), g_x1lo + goff);
    }
#pragma unroll
    for (int it = 0; it < 4; it++) {
        int chunk = it * 256 + tid;
        int row = chunk >> 2, col8 = (chunk & 3) * 8;
        uint32_t sB = sb + G2_OFF_BH + (uint32_t)(row * 40 + col8) * 2;
        cpa16(sB, g_W2hi + row * NCLASS + col8);
    }
    asm volatile("cp.async.commit_group;");
    asm volatile("cp.async.wait_group 0;");
    __syncthreads();

    int warp = tid >> 5, lane = tid & 31;
    int laneRow = lane & 15, laneSeg = (lane >> 4) * 8;
    float acc[4][4];
#pragma unroll
    for (int a = 0; a < 4; a++)
#pragma unroll
        for (int c = 0; c < 4; c++) acc[a][c] = 0.f;

#pragma unroll
    for (int kk = 0; kk < 256; kk += 16) {
        uint32_t ad = sb + G2_OFF_AH + 2u * (uint32_t)((warp * 16 + laneRow) * 264 + kk + laneSeg);
        uint32_t ahf[4], alf[4];
        ldsm4(ahf[0], ahf[1], ahf[2], ahf[3], ad);
        ldsm4(alf[0], alf[1], alf[2], alf[3], ad + (G2_OFF_AL - G2_OFF_AH));
#pragma unroll
        for (int nt = 0; nt < 2; nt++) {
            uint32_t bd = sb + G2_OFF_BH + 2u * (uint32_t)((kk + laneRow) * 40 + nt * 16 + laneSeg);
            uint32_t bh0, bh1, bh2, bh3;
            ldsm4t(bh0, bh1, bh2, bh3, bd);
            mma16816(acc[2 * nt],     ahf, bh0, bh1);
            mma16816(acc[2 * nt],     alf, bh0, bh1);
            mma16816(acc[2 * nt + 1], ahf, bh2, bh3);
            mma16816(acc[2 * nt + 1], alf, bh2, bh3);
        }
    }

    int r0 = blockRow + warp * 16 + (lane >> 2);
    float s1[2] = {0.f, 0.f}, s2[2] = {0.f, 0.f};
#pragma unroll
    for (int n8 = 0; n8 < 4; n8++) {
        int cc = n8 * 8 + (lane & 3) * 2;
        float a0 = __ldg(aout + cc),      a1 = __ldg(aout + cc + 1);
        float b0 = __ldg(aout + 32 + cc), b1 = __ldg(aout + 32 + cc + 1);
        *(float2*)(g_h2 + (size_t)r0 * NCLASS + cc) = make_float2(acc[n8][0], acc[n8][1]);
        *(float2*)(g_h2 + (size_t)(r0 + 8) * NCLASS + cc) = make_float2(acc[n8][2], acc[n8][3]);
        s1[0] += acc[n8][0] * a0 + acc[n8][1] * a1;
        s2[0] += acc[n8][0] * b0 + acc[n8][1] * b1;
        s1[1] += acc[n8][2] * a0 + acc[n8][3] * a1;
        s2[1] += acc[n8][2] * b0 + acc[n8][3] * b1;
    }
#pragma unroll
    for (int hh = 0; hh < 2; hh++) {
        float p1 = s1[hh], p2 = s2[hh];
        p1 += __shfl_xor_sync(0xffffffffu, p1, 1);
        p1 += __shfl_xor_sync(0xffffffffu, p1, 2);
        p2 += __shfl_xor_sync(0xffffffffu, p2, 1);
        p2 += __shfl_xor_sync(0xffffffffu, p2, 2);
        if ((lane & 3) == 0) {
            g_ss2[r0 + hh * 8] = p1;
            g_sd2[r0 + hh * 8] = p2;
        }
    }
}

// ---------------- layer-2 aggregation + elu + log_softmax ------------------
__global__ void agg2_kernel(float* __restrict__ out, int n) {
    int w = (blockIdx.x * blockDim.x + threadIdx.x) >> 5;
    int lane = threadIdx.x & 31;
    if (w >= n) return;
    int start = g_rowptr[w];
    int end = g_rowptr[w + 1];
    float ssn = g_ss2[w];
    float acc = 0.f, rs = 0.f;
    int idx = start;
    for (; idx + 4 <= end; idx += 4) {
        int d0 = g_col[idx], d1 = g_col[idx + 1], d2 = g_col[idx + 2], d3 = g_col[idx + 3];
        float e0 = __expf(-lrelu(ssn + g_sd2[d0]));
        float e1 = __expf(-lrelu(ssn + g_sd2[d1]));
        float e2 = __expf(-lrelu(ssn + g_sd2[d2]));
        float e3 = __expf(-lrelu(ssn + g_sd2[d3]));
        float h0 = g_h2[(size_t)d0 * NCLASS + lane];
        float h1 = g_h2[(size_t)d1 * NCLASS + lane];
        float h2v = g_h2[(size_t)d2 * NCLASS + lane];
        float h3 = g_h2[(size_t)d3 * NCLASS + lane];
        acc += e0 * h0 + e1 * h1 + e2 * h2v + e3 * h3;
        rs += e0 + e1 + e2 + e3;
    }
    for (; idx < end; idx++) {
        int d = g_col[idx];
        float e = __expf(-lrelu(ssn + g_sd2[d]));
        acc += e * g_h2[(size_t)d * NCLASS + lane];
        rs += e;
    }
    float v = eluf(acc / rs);
    float m = v;
#pragma unroll
    for (int off = 16; off; off >>= 1) m = fmaxf(m, __shfl_xor_sync(0xffffffffu, m, off));
    float ex = __expf(v - m);
    float sum = ex;
#pragma unroll
    for (int off = 16; off; off >>= 1) sum += __shfl_xor_sync(0xffffffffu, sum, off);
    out[(size_t)w * NCLASS + lane] = v - m - logf(sum);
}

// ---------------- launch ----------------------------------------------------
extern "C" void kernel_launch(void* const* d_in, const int* in_sizes, int n_in,
                              void* d_out, int out_size) {
    const float* x = (const float*)d_in[0];
    const int* edge = (const int*)d_in[1];
    const float* W_heads = (const float*)d_in[2];
    const float* a_heads = (const float*)d_in[3];
    const float* W_out = (const float*)d_in[4];
    const float* a_out = (const float*)d_in[5];
    float* out = (float*)d_out;

    int n = in_sizes[0] / NFEAT;       // 100000
    int e = in_sizes[1] / 2;           // 1600000
    const int* src = edge;
    const int* dst = edge + e;

    static cudaStream_t s_side = nullptr;
    static cudaEvent_t ev_fork = nullptr, ev_join = nullptr;
    if (s_side == nullptr) {
        cudaFuncSetAttribute(mma_gemm1, cudaFuncAttributeMaxDynamicSharedMemorySize, G1_SMEM);
        cudaFuncSetAttribute(mma_gemm2, cudaFuncAttributeMaxDynamicSharedMemorySize, G2_SMEM);
        cudaStreamCreateWithFlags(&s_side, cudaStreamNonBlocking);
        cudaEventCreateWithFlags(&ev_fork, cudaEventDisableTiming);
        cudaEventCreateWithFlags(&ev_join, cudaEventDisableTiming);
    }

    int prep_elems = NHEADS * NFEAT * NHID;
    int prep_grid = ((prep_elems > n ? prep_elems : n) + 255) / 256;
    prep_kernel<<<prep_grid, 256>>>(W_heads, W_out, n);

    // fork: CSR construction on side stream, overlapped with convx + GEMM1
    cudaEventRecord(ev_fork, 0);
    cudaStreamWaitEvent(s_side, ev_fork, 0);
    hist_kernel<<<(e + 255) / 256, 256, 0, s_side>>>(src, e);
    int nb = (n + 1023) / 1024;
    scan1_kernel<<<nb, 1024, 0, s_side>>>(n);
    scan2_kernel<<<1, 1024, 0, s_side>>>(nb);
    scan3_kernel<<<(n + 255) / 256, 256, 0, s_side>>>(n, e);
    scatter_kernel<<<(e + 255) / 256, 256, 0, s_side>>>(src, dst, e);
    cudaEventRecord(ev_join, s_side);

    // main stream: dense pipeline
    int total8 = n * NFEAT / 8;
    convx_kernel<<<(total8 + 255) / 256, 256>>>(x, total8);

    dim3 g1(HCAT / 128, (n + 127) / 128);
    mma_gemm1<<<g1, 256, G1_SMEM>>>(a_heads, n);

    // join: aggregation needs CSR
    cudaStreamWaitEvent(0, ev_join, 0);

    int nwarp_blocks = (n + 7) / 8;
    agg1_kernel<<<nwarp_blocks, 256>>>(n);
    mma_gemm2<<<(n + 127) / 128, 256, G2_SMEM>>>(a_out);
    agg2_kernel<<<nwarp_blocks, 256>>>(out, n);
}

// round 6
// speedup vs baseline: 3.0278x; 1.1828x over previous
#include <cuda_runtime.h>
#include <cuda_bf16.h>
#include <cuda_fp16.h>
#include <cstdint>

// Problem constants (match reference)
#define NN 100000
#define EE 1600000
#define NFEAT 256
#define NHID 64
#define NHEADS 4
#define HCAT 256   // NHEADS*NHID
#define NCLASS 32
#define ALPHA 0.2f

#define MPAD 128   // row padding so GEMMs need no bounds checks

// ---------------- scratch (device globals; no allocation at runtime) -------
__device__ __half g_Whi[NFEAT * HCAT];
__device__ __half g_W2hi[HCAT * NCLASS];
__device__ __half g_xhi[(size_t)(NN + MPAD) * NFEAT];
__device__ __half g_hcat[(size_t)(NN + MPAD) * HCAT];     // layer-1 features (fp16)
__device__ __half g_x1hi[(size_t)(NN + MPAD) * HCAT];
__device__ float g_ss[(NN + MPAD) * NHEADS];
__device__ float g_sd[(NN + MPAD) * NHEADS];
__device__ int   g_deg[NN];
__device__ int   g_rowptr[NN + 1];
__device__ int   g_cursor[NN];
__device__ int   g_col[EE];
__device__ int   g_blocksums[1024];
__device__ float g_h2[(size_t)(NN + MPAD) * NCLASS];
__device__ float g_ss2[NN + MPAD];
__device__ float g_sd2[NN + MPAD];

__device__ __forceinline__ float eluf(float v) { return v > 0.f ? v : expm1f(v); }
__device__ __forceinline__ float lrelu(float v) { return v > 0.f ? v : ALPHA * v; }

// ---------------- prep: W_heads/W_out -> fp16, concat layout; zero deg ------
__global__ void prep_kernel(const float* __restrict__ Wh, const float* __restrict__ W2, int n) {
    int i = blockIdx.x * blockDim.x + threadIdx.x;
    if (i < NHEADS * NFEAT * NHID) {
        int h = i >> 14;
        int rem = i & 16383;
        int k = rem >> 6;
        int c = rem & 63;
        g_Whi[k * HCAT + (h << 6) + c] = __float2half_rn(Wh[i]);
    }
    if (i < HCAT * NCLASS) {
        g_W2hi[i] = __float2half_rn(W2[i]);
    }
    if (i < n) g_deg[i] = 0;
}

// ---------------- convert x to fp16 (8 floats per thread) ------------------
__global__ void convx_kernel(const float* __restrict__ x, int total8) {
    int i = blockIdx.x * blockDim.x + threadIdx.x;
    if (i >= total8) return;
    const float4* xp = (const float4*)x;
    float4 v0 = xp[i * 2];
    float4 v1 = xp[i * 2 + 1];
    __half hi[8];
    hi[0] = __float2half_rn(v0.x); hi[1] = __float2half_rn(v0.y);
    hi[2] = __float2half_rn(v0.z); hi[3] = __float2half_rn(v0.w);
    hi[4] = __float2half_rn(v1.x); hi[5] = __float2half_rn(v1.y);
    hi[6] = __float2half_rn(v1.z); hi[7] = __float2half_rn(v1.w);
    *(uint4*)(g_xhi + (size_t)i * 8) = *(uint4*)hi;
}

// ---------------- mma helpers -----------------------------------------------
__device__ __forceinline__ void ldsm4(uint32_t& r0, uint32_t& r1, uint32_t& r2, uint32_t& r3, uint32_t addr) {
    asm volatile("ldmatrix.sync.aligned.m8n8.x4.shared.b16 {%0,%1,%2,%3}, [%4];"
                 : "=r"(r0), "=r"(r1), "=r"(r2), "=r"(r3) : "r"(addr));
}
__device__ __forceinline__ void ldsm4t(uint32_t& r0, uint32_t& r1, uint32_t& r2, uint32_t& r3, uint32_t addr) {
    asm volatile("ldmatrix.sync.aligned.m8n8.x4.trans.shared.b16 {%0,%1,%2,%3}, [%4];"
                 : "=r"(r0), "=r"(r1), "=r"(r2), "=r"(r3) : "r"(addr));
}
__device__ __forceinline__ void mma16816(float* c, const uint32_t* a, uint32_t b0, uint32_t b1) {
    asm volatile("mma.sync.aligned.m16n8k16.row.col.f32.f16.f16.f32 "
                 "{%0,%1,%2,%3}, {%4,%5,%6,%7}, {%8,%9}, {%0,%1,%2,%3};"
                 : "+f"(c[0]), "+f"(c[1]), "+f"(c[2]), "+f"(c[3])
                 : "r"(a[0]), "r"(a[1]), "r"(a[2]), "r"(a[3]), "r"(b0), "r"(b1));
}
__device__ __forceinline__ void cpa16(uint32_t s, const void* g) {
    asm volatile("cp.async.cg.shared.global [%0], [%1], 16;" :: "r"(s), "l"(g));
}

// ---------------- GEMM1 + fused layer-1 attention scores --------------------
// smem stage layout (bytes): Ah[128][40]f16, Bh[32][136]f16
#define G1_SS     18944
#define G1_OFF_AH 0
#define G1_OFF_BH 10240
#define G1_SMEM   (2 * G1_SS)

__global__ __launch_bounds__(256, 2) void mma_gemm1(const float* __restrict__ ah, int M) {
    extern __shared__ __align__(16) char dsm[];
    uint32_t sbase = (uint32_t)__cvta_generic_to_shared(dsm);

    int tid = threadIdx.x;
    int lane = tid & 31, warp = tid >> 5;
    int warpM = (warp >> 1) * 32, warpN = (warp & 1) * 64;
    int blockRow = blockIdx.y * 128, blockCol = blockIdx.x * 128;

    int arow0 = tid >> 2,          ac0 = (tid & 3) * 8;
    int arow1 = (tid + 256) >> 2;
    int brow0 = tid >> 4,          bc0 = (tid & 15) * 8;
    int brow1 = (tid + 256) >> 4;

    const __half* gAh0 = g_xhi + (size_t)(blockRow + arow0) * NFEAT + ac0;
    const __half* gAh1 = g_xhi + (size_t)(blockRow + arow1) * NFEAT + ac0;
    const __half* gBh0 = g_Whi + (size_t)brow0 * HCAT + blockCol + bc0;
    const __half* gBh1 = g_Whi + (size_t)brow1 * HCAT + blockCol + bc0;

    uint32_t sA0 = (uint32_t)(arow0 * 40 + ac0) * 2;
    uint32_t sA1 = (uint32_t)(arow1 * 40 + ac0) * 2;
    uint32_t sB0 = (uint32_t)(brow0 * 136 + bc0) * 2;
    uint32_t sB1 = (uint32_t)(brow1 * 136 + bc0) * 2;

    float acc[2][8][4];
#pragma unroll
    for (int a = 0; a < 2; a++)
#pragma unroll
        for (int b = 0; b < 8; b++)
#pragma unroll
            for (int c = 0; c < 4; c++) acc[a][b][c] = 0.f;

    auto load_chunk = [&](int kc, int st) {
        uint32_t sb = sbase + st * G1_SS;
        int k0 = kc * 32;
        cpa16(sb + G1_OFF_AH + sA0, gAh0 + k0);
        cpa16(sb + G1_OFF_AH + sA1, gAh1 + k0);
        cpa16(sb + G1_OFF_BH + sB0, gBh0 + (size_t)k0 * HCAT);
        cpa16(sb + G1_OFF_BH + sB1, gBh1 + (size_t)k0 * HCAT);
        asm volatile("cp.async.commit_group;");
    };

    load_chunk(0, 0);

    int laneRow = lane & 15;
    int laneSeg = (lane >> 4) * 8;

    for (int c = 0; c < 8; c++) {
        int cur = c & 1;
        if (c < 7) load_chunk(c + 1, cur ^ 1);
        if (c < 7) { asm volatile("cp.async.wait_group 1;"); }
        else       { asm volatile("cp.async.wait_group 0;"); }
        __syncthreads();

        uint32_t sb = sbase + cur * G1_SS;
#pragma unroll
        for (int kk = 0; kk < 32; kk += 16) {
            uint32_t ahf[2][4];
#pragma unroll
            for (int mt = 0; mt < 2; mt++) {
                uint32_t ad = sb + G1_OFF_AH +
                    2u * (uint32_t)((warpM + mt * 16 + laneRow) * 40 + kk + laneSeg);
                ldsm4(ahf[mt][0], ahf[mt][1], ahf[mt][2], ahf[mt][3], ad);
            }
#pragma unroll
            for (int nt = 0; nt < 4; nt++) {
                uint32_t bd = sb + G1_OFF_BH +
                    2u * (uint32_t)((kk + laneRow) * 136 + warpN + nt * 16 + laneSeg);
                uint32_t bh0, bh1, bh2, bh3;
                ldsm4t(bh0, bh1, bh2, bh3, bd);
#pragma unroll
                for (int mt = 0; mt < 2; mt++) {
                    mma16816(acc[mt][2 * nt],     ahf[mt], bh0, bh1);
                    mma16816(acc[mt][2 * nt + 1], ahf[mt], bh2, bh3);
                }
            }
        }
        __syncthreads();
    }

    // epilogue: write fp16 hcat + fused attention scores (from fp32 accs)
#pragma unroll
    for (int mt = 0; mt < 2; mt++) {
#pragma unroll
        for (int n8 = 0; n8 < 8; n8++) {
            int r = blockRow + warpM + mt * 16 + (lane >> 2);
            int cc = blockCol + warpN + n8 * 8 + (lane & 3) * 2;
            __half2 p0 = __floats2half2_rn(acc[mt][n8][0], acc[mt][n8][1]);
            __half2 p1 = __floats2half2_rn(acc[mt][n8][2], acc[mt][n8][3]);
            *(__half2*)(g_hcat + (size_t)r * HCAT + cc) = p0;
            *(__half2*)(g_hcat + (size_t)(r + 8) * HCAT + cc) = p1;
        }
    }

    // scores: this warp's 64 cols = exactly one head
    int hd = (blockCol + warpN) >> 6;
    const float* aH = ah + hd * 128;
    float s_src[2][2] = {{0.f, 0.f}, {0.f, 0.f}};
    float s_dst[2][2] = {{0.f, 0.f}, {0.f, 0.f}};
#pragma unroll
    for (int n8 = 0; n8 < 8; n8++) {
        int cc = n8 * 8 + (lane & 3) * 2;
        float a0 = __ldg(aH + cc),      a1 = __ldg(aH + cc + 1);
        float b0 = __ldg(aH + 64 + cc), b1 = __ldg(aH + 64 + cc + 1);
#pragma unroll
        for (int mt = 0; mt < 2; mt++) {
            s_src[mt][0] += acc[mt][n8][0] * a0 + acc[mt][n8][1] * a1;
            s_dst[mt][0] += acc[mt][n8][0] * b0 + acc[mt][n8][1] * b1;
            s_src[mt][1] += acc[mt][n8][2] * a0 + acc[mt][n8][3] * a1;
            s_dst[mt][1] += acc[mt][n8][2] * b0 + acc[mt][n8][3] * b1;
        }
    }
#pragma unroll
    for (int mt = 0; mt < 2; mt++)
#pragma unroll
        for (int hh = 0; hh < 2; hh++) {
            float s1 = s_src[mt][hh], s2 = s_dst[mt][hh];
            s1 += __shfl_xor_sync(0xffffffffu, s1, 1);
            s1 += __shfl_xor_sync(0xffffffffu, s1, 2);
            s2 += __shfl_xor_sync(0xffffffffu, s2, 1);
            s2 += __shfl_xor_sync(0xffffffffu, s2, 2);
            if ((lane & 3) == 0) {
                int r = blockRow + warpM + mt * 16 + (lane >> 2) + hh * 8;
                g_ss[r * NHEADS + hd] = s1;
                g_sd[r * NHEADS + hd] = s2;
            }
        }
}

// ---------------- CSR construction -----------------------------------------
__global__ void hist_kernel(const int* __restrict__ src, int e) {
    int i = blockIdx.x * blockDim.x + threadIdx.x;
    if (i < e) atomicAdd(&g_deg[src[i]], 1);
}

__global__ __launch_bounds__(1024) void scan1_kernel(int n) {
    __shared__ int s[1024];
    int t = threadIdx.x;
    int idx = blockIdx.x * 1024 + t;
    int v = (idx < n) ? g_deg[idx] : 0;
    s[t] = v;
    __syncthreads();
#pragma unroll
    for (int off = 1; off < 1024; off <<= 1) {
        int x = (t >= off) ? s[t - off] : 0;
        __syncthreads();
        s[t] += x;
        __syncthreads();
    }
    if (idx < n) g_rowptr[idx] = s[t] - v;
    if (t == 1023) g_blocksums[blockIdx.x] = s[1023];
}

__global__ __launch_bounds__(1024) void scan2_kernel(int nb) {
    __shared__ int s[1024];
    int t = threadIdx.x;
    int v = (t < nb) ? g_blocksums[t] : 0;
    s[t] = v;
    __syncthreads();
#pragma unroll
    for (int off = 1; off < 1024; off <<= 1) {
        int x = (t >= off) ? s[t - off] : 0;
        __syncthreads();
        s[t] += x;
        __syncthreads();
    }
    if (t < nb) g_blocksums[t] = s[t] - v;
}

__global__ void scan3_kernel(int n, int e) {
    int i = blockIdx.x * blockDim.x + threadIdx.x;
    if (i < n) {
        int r = g_rowptr[i] + g_blocksums[i >> 10];
        g_rowptr[i] = r;
        g_cursor[i] = r;
    }
    if (i == 0) g_rowptr[n] = e;
}

__global__ void scatter_kernel(const int* __restrict__ src, const int* __restrict__ dst, int e) {
    int i = blockIdx.x * blockDim.x + threadIdx.x;
    if (i < e) {
        int s = src[i];
        int p = atomicAdd(&g_cursor[s], 1);
        g_col[p] = dst[i];
    }
}

// ---------------- layer-1 aggregation (warp per src node, fp16 gather) -----
__device__ __forceinline__ void accum8(float* acc, uint4 r, float e) {
    float2 f0 = __half22float2(*(__half2*)&r.x);
    float2 f1 = __half22float2(*(__half2*)&r.y);
    float2 f2 = __half22float2(*(__half2*)&r.z);
    float2 f3 = __half22float2(*(__half2*)&r.w);
    acc[0] += e * f0.x; acc[1] += e * f0.y;
    acc[2] += e * f1.x; acc[3] += e * f1.y;
    acc[4] += e * f2.x; acc[5] += e * f2.y;
    acc[6] += e * f3.x; acc[7] += e * f3.y;
}

__global__ void agg1_kernel(int n) {
    int w = (blockIdx.x * blockDim.x + threadIdx.x) >> 5;
    int lane = threadIdx.x & 31;
    if (w >= n) return;
    int start = g_rowptr[w];
    int end = g_rowptr[w + 1];
    int hd = lane >> 3;                 // head owning this lane's feature slice
    int eidx = lane >> 2;               // edge slot (0..7) for exp duty
    int hidx = lane & 3;                // head for exp duty
    float ss_h = g_ss[w * NHEADS + hidx];
    float acc[8] = {0.f, 0.f, 0.f, 0.f, 0.f, 0.f, 0.f, 0.f};
    float rs32 = 0.f;
    const uint4* hp = (const uint4*)g_hcat;

    int idx = start;
    for (; idx + 8 <= end; idx += 8) {
        int d0 = g_col[idx],     d1 = g_col[idx + 1], d2 = g_col[idx + 2], d3 = g_col[idx + 3];
        int d4 = g_col[idx + 4], d5 = g_col[idx + 5], d6 = g_col[idx + 6], d7 = g_col[idx + 7];
        int dsel;
        switch (eidx) {
            case 0: dsel = d0; break; case 1: dsel = d1; break;
            case 2: dsel = d2; break; case 3: dsel = d3; break;
            case 4: dsel = d4; break; case 5: dsel = d5; break;
            case 6: dsel = d6; break; default: dsel = d7; break;
        }
        float ev = __expf(-lrelu(ss_h + g_sd[dsel * NHEADS + hidx]));
        rs32 += ev;
        uint4 r0 = hp[(size_t)d0 * 32 + lane];
        uint4 r1 = hp[(size_t)d1 * 32 + lane];
        uint4 r2 = hp[(size_t)d2 * 32 + lane];
        uint4 r3 = hp[(size_t)d3 * 32 + lane];
        uint4 r4 = hp[(size_t)d4 * 32 + lane];
        uint4 r5 = hp[(size_t)d5 * 32 + lane];
        uint4 r6 = hp[(size_t)d6 * 32 + lane];
        uint4 r7 = hp[(size_t)d7 * 32 + lane];
        accum8(acc, r0, __shfl_sync(0xffffffffu, ev, 0 * 4 + hd));
        accum8(acc, r1, __shfl_sync(0xffffffffu, ev, 1 * 4 + hd));
        accum8(acc, r2, __shfl_sync(0xffffffffu, ev, 2 * 4 + hd));
        accum8(acc, r3, __shfl_sync(0xffffffffu, ev, 3 * 4 + hd));
        accum8(acc, r4, __shfl_sync(0xffffffffu, ev, 4 * 4 + hd));
        accum8(acc, r5, __shfl_sync(0xffffffffu, ev, 5 * 4 + hd));
        accum8(acc, r6, __shfl_sync(0xffffffffu, ev, 6 * 4 + hd));
        accum8(acc, r7, __shfl_sync(0xffffffffu, ev, 7 * 4 + hd));
    }
    for (; idx < end; idx++) {
        int d = g_col[idx];
        float ev = 0.f;
        if (lane < 4) {
            ev = __expf(-lrelu(ss_h + g_sd[d * NHEADS + hidx]));
            rs32 += ev;
        }
        uint4 r = hp[(size_t)d * 32 + lane];
        accum8(acc, r, __shfl_sync(0xffffffffu, ev, hd));
    }

    // reduce rs over lanes with the same (lane & 3)
    rs32 += __shfl_xor_sync(0xffffffffu, rs32, 4);
    rs32 += __shfl_xor_sync(0xffffffffu, rs32, 8);
    rs32 += __shfl_xor_sync(0xffffffffu, rs32, 16);
    float rs = __shfl_sync(0xffffffffu, rs32, hd);  // lane 'hd' holds head class hd
    float inv = 1.f / rs;

    __half hi8[8];
#pragma unroll
    for (int j = 0; j < 8; j++) {
        hi8[j] = __float2half_rn(eluf(acc[j] * inv));
    }
    *(uint4*)(g_x1hi + (size_t)w * HCAT + lane * 8) = *(uint4*)hi8;
}

// ---------------- GEMM2 (tensor cores) + fused layer-2 scores ---------------
// smem (bytes): Ah[128][264]f16, Bh[256][40]f16
#define G2_OFF_AH 0
#define G2_OFF_BH 67584
#define G2_SMEM   88064

__global__ __launch_bounds__(256) void mma_gemm2(const float* __restrict__ aout) {
    extern __shared__ __align__(16) char dsm[];
    uint32_t sb = (uint32_t)__cvta_generic_to_shared(dsm);
    int tid = threadIdx.x;
    int blockRow = blockIdx.x * 128;

#pragma unroll
    for (int it = 0; it < 16; it++) {
        int chunk = it * 256 + tid;
        int row = chunk >> 5, col8 = (chunk & 31) * 8;
        size_t goff = (size_t)(blockRow + row) * HCAT + col8;
        uint32_t sa = sb + G2_OFF_AH + (uint32_t)(row * 264 + col8) * 2;
        cpa16(sa, g_x1hi + goff);
    }
#pragma unroll
    for (int it = 0; it < 4; it++) {
        int chunk = it * 256 + tid;
        int row = chunk >> 2, col8 = (chunk & 3) * 8;
        uint32_t sB = sb + G2_OFF_BH + (uint32_t)(row * 40 + col8) * 2;
        cpa16(sB, g_W2hi + row * NCLASS + col8);
    }
    asm volatile("cp.async.commit_group;");
    asm volatile("cp.async.wait_group 0;");
    __syncthreads();

    int warp = tid >> 5, lane = tid & 31;
    int laneRow = lane & 15, laneSeg = (lane >> 4) * 8;
    float acc[4][4];
#pragma unroll
    for (int a = 0; a < 4; a++)
#pragma unroll
        for (int c = 0; c < 4; c++) acc[a][c] = 0.f;

#pragma unroll
    for (int kk = 0; kk < 256; kk += 16) {
        uint32_t ad = sb + G2_OFF_AH + 2u * (uint32_t)((warp * 16 + laneRow) * 264 + kk + laneSeg);
        uint32_t ahf[4];
        ldsm4(ahf[0], ahf[1], ahf[2], ahf[3], ad);
#pragma unroll
        for (int nt = 0; nt < 2; nt++) {
            uint32_t bd = sb + G2_OFF_BH + 2u * (uint32_t)((kk + laneRow) * 40 + nt * 16 + laneSeg);
            uint32_t bh0, bh1, bh2, bh3;
            ldsm4t(bh0, bh1, bh2, bh3, bd);
            mma16816(acc[2 * nt],     ahf, bh0, bh1);
            mma16816(acc[2 * nt + 1], ahf, bh2, bh3);
        }
    }

    int r0 = blockRow + warp * 16 + (lane >> 2);
    float s1[2] = {0.f, 0.f}, s2[2] = {0.f, 0.f};
#pragma unroll
    for (int n8 = 0; n8 < 4; n8++) {
        int cc = n8 * 8 + (lane & 3) * 2;
        float a0 = __ldg(aout + cc),      a1 = __ldg(aout + cc + 1);
        float b0 = __ldg(aout + 32 + cc), b1 = __ldg(aout + 32 + cc + 1);
        *(float2*)(g_h2 + (size_t)r0 * NCLASS + cc) = make_float2(acc[n8][0], acc[n8][1]);
        *(float2*)(g_h2 + (size_t)(r0 + 8) * NCLASS + cc) = make_float2(acc[n8][2], acc[n8][3]);
        s1[0] += acc[n8][0] * a0 + acc[n8][1] * a1;
        s2[0] += acc[n8][0] * b0 + acc[n8][1] * b1;
        s1[1] += acc[n8][2] * a0 + acc[n8][3] * a1;
        s2[1] += acc[n8][2] * b0 + acc[n8][3] * b1;
    }
#pragma unroll
    for (int hh = 0; hh < 2; hh++) {
        float p1 = s1[hh], p2 = s2[hh];
        p1 += __shfl_xor_sync(0xffffffffu, p1, 1);
        p1 += __shfl_xor_sync(0xffffffffu, p1, 2);
        p2 += __shfl_xor_sync(0xffffffffu, p2, 1);
        p2 += __shfl_xor_sync(0xffffffffu, p2, 2);
        if ((lane & 3) == 0) {
            g_ss2[r0 + hh * 8] = p1;
            g_sd2[r0 + hh * 8] = p2;
        }
    }
}

// ---------------- layer-2 aggregation + elu + log_softmax ------------------
__global__ void agg2_kernel(float* __restrict__ out, int n) {
    int w = (blockIdx.x * blockDim.x + threadIdx.x) >> 5;
    int lane = threadIdx.x & 31;
    if (w >= n) return;
    int start = g_rowptr[w];
    int end = g_rowptr[w + 1];
    float ssn = g_ss2[w];
    float acc = 0.f, rs = 0.f;
    int idx = start;
    for (; idx + 8 <= end; idx += 8) {
        int d[8];
#pragma unroll
        for (int j = 0; j < 8; j++) d[j] = g_col[idx + j];
        float ev[8], hv[8];
#pragma unroll
        for (int j = 0; j < 8; j++) ev[j] = __expf(-lrelu(ssn + g_sd2[d[j]]));
#pragma unroll
        for (int j = 0; j < 8; j++) hv[j] = g_h2[(size_t)d[j] * NCLASS + lane];
#pragma unroll
        for (int j = 0; j < 8; j++) { acc += ev[j] * hv[j]; rs += ev[j]; }
    }
    for (; idx < end; idx++) {
        int d = g_col[idx];
        float e = __expf(-lrelu(ssn + g_sd2[d]));
        acc += e * g_h2[(size_t)d * NCLASS + lane];
        rs += e;
    }
    float v = eluf(acc / rs);
    float m = v;
#pragma unroll
    for (int off = 16; off; off >>= 1) m = fmaxf(m, __shfl_xor_sync(0xffffffffu, m, off));
    float ex = __expf(v - m);
    float sum = ex;
#pragma unroll
    for (int off = 16; off; off >>= 1) sum += __shfl_xor_sync(0xffffffffu, sum, off);
    out[(size_t)w * NCLASS + lane] = v - m - logf(sum);
}

// ---------------- launch ----------------------------------------------------
extern "C" void kernel_launch(void* const* d_in, const int* in_sizes, int n_in,
                              void* d_out, int out_size) {
    const float* x = (const float*)d_in[0];
    const int* edge = (const int*)d_in[1];
    const float* W_heads = (const float*)d_in[2];
    const float* a_heads = (const float*)d_in[3];
    const float* W_out = (const float*)d_in[4];
    const float* a_out = (const float*)d_in[5];
    float* out = (float*)d_out;

    int n = in_sizes[0] / NFEAT;       // 100000
    int e = in_sizes[1] / 2;           // 1600000
    const int* src = edge;
    const int* dst = edge + e;

    static cudaStream_t s_side = nullptr;
    static cudaEvent_t ev_fork = nullptr, ev_join = nullptr;
    if (s_side == nullptr) {
        cudaFuncSetAttribute(mma_gemm1, cudaFuncAttributeMaxDynamicSharedMemorySize, G1_SMEM);
        cudaFuncSetAttribute(mma_gemm2, cudaFuncAttributeMaxDynamicSharedMemorySize, G2_SMEM);
        cudaStreamCreateWithFlags(&s_side, cudaStreamNonBlocking);
        cudaEventCreateWithFlags(&ev_fork, cudaEventDisableTiming);
        cudaEventCreateWithFlags(&ev_join, cudaEventDisableTiming);
    }

    int prep_elems = NHEADS * NFEAT * NHID;
    int prep_grid = ((prep_elems > n ? prep_elems : n) + 255) / 256;
    prep_kernel<<<prep_grid, 256>>>(W_heads, W_out, n);

    // fork: CSR construction on side stream, overlapped with convx + GEMM1
    cudaEventRecord(ev_fork, 0);
    cudaStreamWaitEvent(s_side, ev_fork, 0);
    hist_kernel<<<(e + 255) / 256, 256, 0, s_side>>>(src, e);
    int nb = (n + 1023) / 1024;
    scan1_kernel<<<nb, 1024, 0, s_side>>>(n);
    scan2_kernel<<<1, 1024, 0, s_side>>>(nb);
    scan3_kernel<<<(n + 255) / 256, 256, 0, s_side>>>(n, e);
    scatter_kernel<<<(e + 255) / 256, 256, 0, s_side>>>(src, dst, e);
    cudaEventRecord(ev_join, s_side);

    // main stream: dense pipeline
    int total8 = n * NFEAT / 8;
    convx_kernel<<<(total8 + 255) / 256, 256>>>(x, total8);

    dim3 g1(HCAT / 128, (n + 127) / 128);
    mma_gemm1<<<g1, 256, G1_SMEM>>>(a_heads, n);

    // join: aggregation needs CSR
    cudaStreamWaitEvent(0, ev_join, 0);

    int nwarp_blocks = (n + 7) / 8;
    agg1_kernel<<<nwarp_blocks, 256>>>(n);
    mma_gemm2<<<(n + 127) / 128, 256, G2_SMEM>>>(a_out);
    agg2_kernel<<<nwarp_blocks, 256>>>(out, n);
}